// round 1
// baseline (speedup 1.0000x reference)
#include <cuda_runtime.h>
#include <math.h>

#define NN 131072
#define EE 1048576
#define HH 256
#define WW 256

// ---------------- scratch (device globals; no allocations) ----------------
__device__ float g_h0[NN * 64];    // conv+bn2+elu output
__device__ float g_hw[NN * 64];    // h0 @ gcn_w.T
__device__ float g_h1[NN * 64];    // gcn output after bn1+elu
__device__ float g_q[NN * 64];
__device__ float g_k[NN * 64];
__device__ float g_v[NN * 64];
__device__ float g_acc[NN * 64];   // gcn aggregation accumulator
__device__ float g_acc2[NN * 64];  // skip + attention messages
__device__ float g_deg[NN];
__device__ float g_dinv[NN];
__device__ float g_amax[NN];
__device__ float g_denom[NN];
__device__ float g_alpha[EE];      // alpha, then overwritten with ex

__device__ __forceinline__ float eluf(float x) {
    return x > 0.f ? x : 0.1f * expm1f(x);
}

// float atomic max via signed(int)/unsigned(min) ordering trick
__device__ __forceinline__ void atomicMaxF(float* addr, float val) {
    if (val >= 0.f) atomicMax((int*)addr, __float_as_int(val));
    else            atomicMin((unsigned int*)addr, __float_as_uint(val));
}

// ---------------- init ----------------
__global__ void k_init() {
    int i = blockIdx.x * blockDim.x + threadIdx.x;
    if (i < NN) {
        g_deg[i]   = 2.0f;       // self-loop weight
        g_amax[i]  = -INFINITY;
        g_denom[i] = 0.0f;
    }
}

// ---------------- degree: deg[col] += ew[:,1] ----------------
__global__ void k_deg(const int* __restrict__ ei, const float* __restrict__ ew) {
    int e = blockIdx.x * blockDim.x + threadIdx.x;
    if (e < EE) {
        int c = ei[EE + e];
        atomicAdd(&g_deg[c], ew[2 * e + 1]);
    }
}

// ---------------- conv 3x3 SAME + bn2 + elu ----------------
// block: 256 threads = 64 pixels x 4 channel-groups of 16. grid: 2*256*4 = 2048
__global__ void k_conv(const float* __restrict__ x, const float* __restrict__ cw,
                       const float* __restrict__ bg, const float* __restrict__ bb,
                       const float* __restrict__ bm, const float* __restrict__ bv) {
    extern __shared__ float sm[];
    float* ws  = sm;            // [ky*3+kx][ci][co] : 9*32*64 = 18432 floats
    float* ins = sm + 18432;    // 3 rows x 66 px, stride 33 per pixel (pad)

    int tid = threadIdx.x;
    int bid = blockIdx.x;
    int xt = bid & 3;
    int y  = (bid >> 2) & 255;
    int b  = bid >> 10;
    int x0 = xt * 64;

    for (int i = tid; i < 18432; i += 256) {
        int co = i & 63;
        int ci = (i >> 6) & 31;
        int kk = i >> 11;
        int ky = kk / 3, kx = kk - ky * 3;
        ws[i] = cw[((co * 32 + ci) * 3 + ky) * 3 + kx];
    }
    for (int i = tid; i < 3 * 66 * 32; i += 256) {
        int ci = i & 31;
        int p  = i >> 5;
        int r  = p / 66;
        int px = p - r * 66;
        int yy = y + r - 1;
        int xx = x0 + px - 1;
        float val = 0.f;
        if (yy >= 0 && yy < HH && xx >= 0 && xx < WW)
            val = x[(((size_t)b * HH + yy) * WW + xx) * 32 + ci];
        ins[(r * 66 + px) * 33 + ci] = val;
    }
    __syncthreads();

    int px  = tid & 63;
    int co0 = (tid >> 6) << 4;
    float acc[16];
#pragma unroll
    for (int j = 0; j < 16; j++) acc[j] = 0.f;

#pragma unroll
    for (int ky = 0; ky < 3; ky++)
#pragma unroll
        for (int kx = 0; kx < 3; kx++) {
            const float* ip = &ins[(ky * 66 + px + kx) * 33];
            const float* wp = &ws[((ky * 3 + kx) * 32) * 64 + co0];
#pragma unroll 8
            for (int ci = 0; ci < 32; ci++) {
                float iv = ip[ci];
                const float4* w4 = (const float4*)(wp + ci * 64);
                float4 a = w4[0], bq = w4[1], cq = w4[2], dq = w4[3];
                acc[0]  += iv * a.x;  acc[1]  += iv * a.y;  acc[2]  += iv * a.z;  acc[3]  += iv * a.w;
                acc[4]  += iv * bq.x; acc[5]  += iv * bq.y; acc[6]  += iv * bq.z; acc[7]  += iv * bq.w;
                acc[8]  += iv * cq.x; acc[9]  += iv * cq.y; acc[10] += iv * cq.z; acc[11] += iv * cq.w;
                acc[12] += iv * dq.x; acc[13] += iv * dq.y; acc[14] += iv * dq.z; acc[15] += iv * dq.w;
            }
        }

    size_t pix = ((size_t)b * HH + y) * WW + x0 + px;
    float res[16];
#pragma unroll
    for (int j = 0; j < 16; j++) {
        int c = co0 + j;
        float sc = __ldg(&bg[c]) * rsqrtf(__ldg(&bv[c]) + 1e-5f);
        float vv = (acc[j] - __ldg(&bm[c])) * sc + __ldg(&bb[c]);
        res[j] = eluf(vv);
    }
    float4* o4 = (float4*)(g_h0 + pix * 64 + co0);
    o4[0] = make_float4(res[0], res[1], res[2], res[3]);
    o4[1] = make_float4(res[4], res[5], res[6], res[7]);
    o4[2] = make_float4(res[8], res[9], res[10], res[11]);
    o4[3] = make_float4(res[12], res[13], res[14], res[15]);
}

// ---------------- generic (N,64) @ (64,64)^T + bias ----------------
// block 256 threads, 64 nodes per block. out[i][co] = sum_ci in[i][ci]*W[co][ci] + b[co]
__global__ void k_gemm64(const float* __restrict__ in, const float* __restrict__ Wm,
                         const float* __restrict__ bias, float* __restrict__ out) {
    __shared__ float insm[64 * 65];
    __shared__ float wsm[4096];   // wsm[ci*64+co]
    __shared__ float bsm[64];
    int tid = threadIdx.x;
    size_t base = (size_t)blockIdx.x * 4096;
    for (int i = tid; i < 4096; i += 256) {
        int r = i >> 6, c = i & 63;
        insm[r * 65 + c] = in[base + i];
        wsm[c * 64 + r]  = Wm[i];
    }
    if (tid < 64) bsm[tid] = bias ? bias[tid] : 0.f;
    __syncthreads();

    int n   = tid >> 2;
    int co0 = (tid & 3) << 4;
    const float* ip = insm + n * 65;
    float acc[16];
#pragma unroll
    for (int j = 0; j < 16; j++) acc[j] = bsm[co0 + j];
#pragma unroll 8
    for (int ci = 0; ci < 64; ci++) {
        float xv = ip[ci];
        const float4* w4 = (const float4*)(wsm + ci * 64 + co0);
        float4 a = w4[0], bq = w4[1], cq = w4[2], dq = w4[3];
        acc[0]  += xv * a.x;  acc[1]  += xv * a.y;  acc[2]  += xv * a.z;  acc[3]  += xv * a.w;
        acc[4]  += xv * bq.x; acc[5]  += xv * bq.y; acc[6]  += xv * bq.z; acc[7]  += xv * bq.w;
        acc[8]  += xv * cq.x; acc[9]  += xv * cq.y; acc[10] += xv * cq.z; acc[11] += xv * cq.w;
        acc[12] += xv * dq.x; acc[13] += xv * dq.y; acc[14] += xv * dq.z; acc[15] += xv * dq.w;
    }
    float4* o4 = (float4*)(out + base + n * 64 + co0);
    o4[0] = make_float4(acc[0], acc[1], acc[2], acc[3]);
    o4[1] = make_float4(acc[4], acc[5], acc[6], acc[7]);
    o4[2] = make_float4(acc[8], acc[9], acc[10], acc[11]);
    o4[3] = make_float4(acc[12], acc[13], acc[14], acc[15]);
}

// ---------------- gcn: dinv + self-loop init of accumulator ----------------
__global__ void k_gcn_init() {
    int gid = blockIdx.x * blockDim.x + threadIdx.x;  // NN*16 threads
    int i = gid >> 4, qd = gid & 15;
    float d = g_deg[i];
    if (qd == 0) g_dinv[i] = rsqrtf(d);
    float s = 2.0f / d;  // dinv * 2 * dinv
    float4 h4 = ((const float4*)g_hw)[(size_t)i * 16 + qd];
    ((float4*)g_acc)[(size_t)i * 16 + qd] = make_float4(s * h4.x, s * h4.y, s * h4.z, s * h4.w);
}

// ---------------- gcn edge scatter ----------------
__global__ void k_gcn_scatter(const int* __restrict__ ei, const float* __restrict__ ew) {
    int gid = blockIdx.x * blockDim.x + threadIdx.x;  // EE*16 threads
    int e = gid >> 4, qd = gid & 15;
    int r = ei[e], c = ei[EE + e];
    float coeff = g_dinv[r] * g_dinv[c] * ew[2 * e + 1];
    float4 h4 = ((const float4*)g_hw)[(size_t)r * 16 + qd];
    float* dst = g_acc + (size_t)c * 64 + qd * 4;
    atomicAdd(dst + 0, coeff * h4.x);
    atomicAdd(dst + 1, coeff * h4.y);
    atomicAdd(dst + 2, coeff * h4.z);
    atomicAdd(dst + 3, coeff * h4.w);
}

// ---------------- gcn finalize: +gcn_b, bn1, elu -> h1 ----------------
__global__ void k_gcn_final(const float* __restrict__ gb,
                            const float* __restrict__ g1, const float* __restrict__ b1,
                            const float* __restrict__ m1, const float* __restrict__ v1) {
    int gid = blockIdx.x * blockDim.x + threadIdx.x;  // NN*16
    int i = gid >> 4, qd = gid & 15;
    float4 a4 = ((const float4*)g_acc)[(size_t)i * 16 + qd];
    int c0 = qd * 4;
    float r[4] = {a4.x, a4.y, a4.z, a4.w};
#pragma unroll
    for (int j = 0; j < 4; j++) {
        int c = c0 + j;
        float val = r[j] + __ldg(&gb[c]);
        float sc = __ldg(&g1[c]) * rsqrtf(__ldg(&v1[c]) + 1e-5f);
        r[j] = eluf((val - __ldg(&m1[c])) * sc + __ldg(&b1[c]));
    }
    ((float4*)g_h1)[(size_t)i * 16 + qd] = make_float4(r[0], r[1], r[2], r[3]);
}

// ---------------- attention alpha + segment max (warp per edge) ----------------
__global__ void k_alpha(const int* __restrict__ ei, const float* __restrict__ ew,
                        const float* __restrict__ we) {
    __shared__ float wesm[128];
    int tid = threadIdx.x;
    if (tid < 128) wesm[tid] = we[tid];
    __syncthreads();
    int e = blockIdx.x * 8 + (tid >> 5);
    int lane = tid & 31;
    int r = ei[e], c = ei[EE + e];
    float2 ewv = ((const float2*)ew)[e];
    float2 q2 = ((const float2*)g_q)[(size_t)c * 32 + lane];
    float2 k2 = ((const float2*)g_k)[(size_t)r * 32 + lane];
    float2 w0 = ((const float2*)wesm)[2 * lane];
    float2 w1 = ((const float2*)wesm)[2 * lane + 1];
    float s = q2.x * (k2.x + w0.x * ewv.x + w0.y * ewv.y)
            + q2.y * (k2.y + w1.x * ewv.x + w1.y * ewv.y);
#pragma unroll
    for (int o = 16; o; o >>= 1) s += __shfl_xor_sync(0xffffffffu, s, o);
    if (lane == 0) {
        s *= 0.125f;  // 1/sqrt(64)
        g_alpha[e] = s;
        atomicMaxF(&g_amax[c], s);
    }
}

// ---------------- ex + denom (thread per edge); overwrites g_alpha with ex ----
__global__ void k_denom(const int* __restrict__ ei) {
    int e = blockIdx.x * blockDim.x + threadIdx.x;
    if (e < EE) {
        int c = ei[EE + e];
        float ex = expf(g_alpha[e] - g_amax[c]);
        g_alpha[e] = ex;
        atomicAdd(&g_denom[c], ex);
    }
}

// ---------------- message scatter: acc2[col] += (v[row]+e)*attn --------------
__global__ void k_msg(const int* __restrict__ ei, const float* __restrict__ ew,
                      const float* __restrict__ we) {
    __shared__ float wesm[128];
    int tid = threadIdx.x;
    if (tid < 128) wesm[tid] = we[tid];
    __syncthreads();
    int gid = blockIdx.x * 256 + tid;  // EE*16 threads
    int e = gid >> 4, qd = gid & 15;
    int r = ei[e], c = ei[EE + e];
    float2 ewv = ((const float2*)ew)[e];
    float attn = g_alpha[e] / g_denom[c];
    float4 v4 = ((const float4*)g_v)[(size_t)r * 16 + qd];
    int c0 = qd * 4;
    float m0 = (v4.x + wesm[2 * c0 + 0] * ewv.x + wesm[2 * c0 + 1] * ewv.y) * attn;
    float m1 = (v4.y + wesm[2 * c0 + 2] * ewv.x + wesm[2 * c0 + 3] * ewv.y) * attn;
    float m2 = (v4.z + wesm[2 * c0 + 4] * ewv.x + wesm[2 * c0 + 5] * ewv.y) * attn;
    float m3 = (v4.w + wesm[2 * c0 + 6] * ewv.x + wesm[2 * c0 + 7] * ewv.y) * attn;
    float* dst = g_acc2 + (size_t)c * 64 + c0;
    atomicAdd(dst + 0, m0);
    atomicAdd(dst + 1, m1);
    atomicAdd(dst + 2, m2);
    atomicAdd(dst + 3, m3);
}

// ---------------- final: bn1(acc2) @ wl.T + bl (warp per node) ---------------
__global__ void k_final(const float* __restrict__ g1, const float* __restrict__ b1,
                        const float* __restrict__ m1, const float* __restrict__ v1,
                        const float* __restrict__ wl, const float* __restrict__ bl,
                        float* __restrict__ out) {
    int t = blockIdx.x * blockDim.x + threadIdx.x;  // NN*32 threads
    int node = t >> 5, lane = t & 31;
    float2 a2 = ((const float2*)g_acc2)[(size_t)node * 32 + lane];
    int c0 = lane * 2;
    float s0 = __ldg(&g1[c0]) * rsqrtf(__ldg(&v1[c0]) + 1e-5f);
    float s1 = __ldg(&g1[c0 + 1]) * rsqrtf(__ldg(&v1[c0 + 1]) + 1e-5f);
    float x0 = (a2.x - __ldg(&m1[c0])) * s0 + __ldg(&b1[c0]);
    float x1 = (a2.y - __ldg(&m1[c0 + 1])) * s1 + __ldg(&b1[c0 + 1]);
    float s = x0 * __ldg(&wl[c0]) + x1 * __ldg(&wl[c0 + 1]);
#pragma unroll
    for (int o = 16; o; o >>= 1) s += __shfl_xor_sync(0xffffffffu, s, o);
    if (lane == 0) out[node] = s + __ldg(&bl[0]);
}

// ---------------- host launcher ----------------
extern "C" void kernel_launch(void* const* d_in, const int* in_sizes, int n_in,
                              void* d_out, int out_size) {
    (void)in_sizes; (void)n_in; (void)out_size;
    const float* x     = (const float*)d_in[0];
    const int*   ei    = (const int*)d_in[1];
    const float* ew    = (const float*)d_in[2];
    // d_in[3] batch (unused), d_in[4] nrows, d_in[5] ncols (constants)
    const float* cw    = (const float*)d_in[6];
    const float* bn2g  = (const float*)d_in[7];
    const float* bn2b  = (const float*)d_in[8];
    const float* bn2m  = (const float*)d_in[9];
    const float* bn2v  = (const float*)d_in[10];
    const float* gcnw  = (const float*)d_in[11];
    const float* gcnb  = (const float*)d_in[12];
    const float* bn1g  = (const float*)d_in[13];
    const float* bn1b  = (const float*)d_in[14];
    const float* bn1m  = (const float*)d_in[15];
    const float* bn1v  = (const float*)d_in[16];
    const float* wq    = (const float*)d_in[17];
    const float* bq    = (const float*)d_in[18];
    const float* wk    = (const float*)d_in[19];
    const float* bk    = (const float*)d_in[20];
    const float* wv    = (const float*)d_in[21];
    const float* bv    = (const float*)d_in[22];
    const float* we    = (const float*)d_in[23];
    const float* wsk   = (const float*)d_in[24];
    const float* bsk   = (const float*)d_in[25];
    const float* wl    = (const float*)d_in[26];
    const float* bl    = (const float*)d_in[27];

    float *p_h0, *p_hw, *p_h1, *p_q, *p_k, *p_v, *p_acc2;
    cudaGetSymbolAddress((void**)&p_h0,   g_h0);
    cudaGetSymbolAddress((void**)&p_hw,   g_hw);
    cudaGetSymbolAddress((void**)&p_h1,   g_h1);
    cudaGetSymbolAddress((void**)&p_q,    g_q);
    cudaGetSymbolAddress((void**)&p_k,    g_k);
    cudaGetSymbolAddress((void**)&p_v,    g_v);
    cudaGetSymbolAddress((void**)&p_acc2, g_acc2);

    const int conv_smem = (18432 + 3 * 66 * 33) * 4;
    cudaFuncSetAttribute(k_conv, cudaFuncAttributeMaxDynamicSharedMemorySize, conv_smem);

    k_init<<<NN / 256, 256>>>();
    k_deg<<<EE / 256, 256>>>(ei, ew);
    k_conv<<<2048, 256, conv_smem>>>(x, cw, bn2g, bn2b, bn2m, bn2v);
    k_gemm64<<<NN / 64, 256>>>(p_h0, gcnw, nullptr, p_hw);
    k_gcn_init<<<NN * 16 / 256, 256>>>();
    k_gcn_scatter<<<EE * 16 / 256, 256>>>(ei, ew);
    k_gcn_final<<<NN * 16 / 256, 256>>>(gcnb, bn1g, bn1b, bn1m, bn1v);
    k_gemm64<<<NN / 64, 256>>>(p_h1, wq, bq, p_q);
    k_gemm64<<<NN / 64, 256>>>(p_h1, wk, bk, p_k);
    k_gemm64<<<NN / 64, 256>>>(p_h1, wv, bv, p_v);
    k_gemm64<<<NN / 64, 256>>>(p_h1, wsk, bsk, p_acc2);
    k_alpha<<<EE / 8, 256>>>(ei, ew, we);
    k_denom<<<EE / 256, 256>>>(ei);
    k_msg<<<EE * 16 / 256, 256>>>(ei, ew, we);
    k_final<<<NN * 32 / 256, 256>>>(bn1g, bn1b, bn1m, bn1v, wl, bl, (float*)d_out);
}

// round 2
// speedup vs baseline: 1.7471x; 1.7471x over previous
#include <cuda_runtime.h>
#include <math.h>

#define NN 131072
#define EE 1048576
#define HH 256
#define WW 256

// ---------------- scratch (device globals; no allocations) ----------------
__device__ float g_h0[NN * 64];    // conv+bn2+elu output
__device__ float g_hw[NN * 64];    // h0 @ gcn_w.T
__device__ float g_h1[NN * 64];    // gcn output after bn1+elu
__device__ float g_q[NN * 64];
__device__ float g_k[NN * 64];
__device__ float g_v[NN * 64];
__device__ float g_acc[NN * 64];   // gcn aggregation accumulator
__device__ float g_acc2[NN * 64];  // skip + attention messages
__device__ float g_deg[NN];
__device__ float g_dinv[NN];
__device__ float g_amax[NN];
__device__ float g_denom[NN];
__device__ float g_alpha[EE];      // alpha, then overwritten with ex

__device__ __forceinline__ float eluf(float x) {
    return x > 0.f ? x : 0.1f * expm1f(x);
}

__device__ __forceinline__ void atomicMaxF(float* addr, float val) {
    if (val >= 0.f) atomicMax((int*)addr, __float_as_int(val));
    else            atomicMin((unsigned int*)addr, __float_as_uint(val));
}

__device__ __forceinline__ void redAdd4(float* dst, float a, float b, float c, float d) {
    asm volatile("red.global.add.v4.f32 [%0], {%1,%2,%3,%4};"
                 :: "l"(dst), "f"(a), "f"(b), "f"(c), "f"(d) : "memory");
}

// ---------------- init ----------------
__global__ void k_init() {
    int i = blockIdx.x * blockDim.x + threadIdx.x;
    if (i < NN) {
        g_deg[i]   = 2.0f;       // self-loop weight
        g_amax[i]  = -INFINITY;
        g_denom[i] = 0.0f;
    }
}

// ---------------- degree: deg[col] += ew[:,1] ----------------
__global__ void k_deg(const int* __restrict__ ei, const float* __restrict__ ew) {
    int e = blockIdx.x * blockDim.x + threadIdx.x;
    if (e < EE) {
        int c = ei[EE + e];
        atomicAdd(&g_deg[c], ew[2 * e + 1]);
    }
}

// ---------------- conv 3x3 SAME + bn2 + elu ----------------
// block: 256 threads; tile 64 px x 64 co; micro-tile 4 px x 4 co per thread.
__global__ void k_conv(const float* __restrict__ x, const float* __restrict__ cw,
                       const float* __restrict__ bg, const float* __restrict__ bb,
                       const float* __restrict__ bm, const float* __restrict__ bv) {
    extern __shared__ float sm[];
    float* ws  = sm;            // [k][ci][co] : 9*32*64 = 18432 floats
    float* ins = sm + 18432;    // [ci][r][px] : 32*3*68 floats (px 0..65 valid)

    int tid = threadIdx.x;
    int bid = blockIdx.x;
    int xt = bid & 3;
    int y  = (bid >> 2) & 255;
    int b  = bid >> 10;
    int x0 = xt * 64;

    // weights: ws[k*32*64 + ci*64 + co]
    for (int i = tid; i < 18432; i += 256) {
        int co = i & 63;
        int ci = (i >> 6) & 31;
        int kk = i >> 11;
        int ky = kk / 3, kx = kk - ky * 3;
        ws[i] = cw[((co * 32 + ci) * 3 + ky) * 3 + kx];
    }
    // input halo: 3 rows x 66 px x 32 ch, channel-major
    for (int i = tid; i < 3 * 66 * 32; i += 256) {
        int ci = i & 31;
        int p  = i >> 5;
        int r  = p / 66;
        int px = p - r * 66;
        int yy = y + r - 1;
        int xx = x0 + px - 1;
        float val = 0.f;
        if (yy >= 0 && yy < HH && xx >= 0 && xx < WW)
            val = x[(((size_t)b * HH + yy) * WW + xx) * 32 + ci];
        ins[ci * 204 + r * 68 + px] = val;
    }
    __syncthreads();

    int tx = tid & 15;         // co group
    int ty = tid >> 4;         // px group
    int co0 = tx * 4;
    int px0 = ty * 4;

    float acc[4][4];
#pragma unroll
    for (int i = 0; i < 4; i++)
#pragma unroll
        for (int j = 0; j < 4; j++) acc[i][j] = 0.f;

#pragma unroll
    for (int ky = 0; ky < 3; ky++)
#pragma unroll
        for (int kx = 0; kx < 3; kx++) {
            int k = ky * 3 + kx;
            const float* ip = ins + ky * 68 + px0 + kx;   // + ci*204
            const float* wp = ws + k * 2048 + co0;        // + ci*64
#pragma unroll 4
            for (int ci = 0; ci < 32; ci++) {
                float4 w = *(const float4*)(wp + ci * 64);
                const float* ipc = ip + ci * 204;
                float a0 = ipc[0], a1 = ipc[1], a2 = ipc[2], a3 = ipc[3];
                acc[0][0] += a0 * w.x; acc[0][1] += a0 * w.y; acc[0][2] += a0 * w.z; acc[0][3] += a0 * w.w;
                acc[1][0] += a1 * w.x; acc[1][1] += a1 * w.y; acc[1][2] += a1 * w.z; acc[1][3] += a1 * w.w;
                acc[2][0] += a2 * w.x; acc[2][1] += a2 * w.y; acc[2][2] += a2 * w.z; acc[2][3] += a2 * w.w;
                acc[3][0] += a3 * w.x; acc[3][1] += a3 * w.y; acc[3][2] += a3 * w.z; acc[3][3] += a3 * w.w;
            }
        }

    // bn2 + elu epilogue
    float sc[4], mm[4], bbv[4];
#pragma unroll
    for (int j = 0; j < 4; j++) {
        int c = co0 + j;
        sc[j]  = __ldg(&bg[c]) * rsqrtf(__ldg(&bv[c]) + 1e-5f);
        mm[j]  = __ldg(&bm[c]);
        bbv[j] = __ldg(&bb[c]);
    }
    size_t pixbase = ((size_t)b * HH + y) * WW + x0 + px0;
#pragma unroll
    for (int i = 0; i < 4; i++) {
        float r0 = eluf((acc[i][0] - mm[0]) * sc[0] + bbv[0]);
        float r1 = eluf((acc[i][1] - mm[1]) * sc[1] + bbv[1]);
        float r2 = eluf((acc[i][2] - mm[2]) * sc[2] + bbv[2]);
        float r3 = eluf((acc[i][3] - mm[3]) * sc[3] + bbv[3]);
        *(float4*)(g_h0 + (pixbase + i) * 64 + co0) = make_float4(r0, r1, r2, r3);
    }
}

// ---------------- (N,64) @ (64,64)^T + bias, 128x64 tile, 8x4 micro ----------
__global__ void k_gemm(const float* __restrict__ in, const float* __restrict__ Wm,
                       const float* __restrict__ bias, float* __restrict__ out) {
    __shared__ float insm[128][68];
    __shared__ float ws[64][68];   // ws[ci][co]
    __shared__ float bsm[64];
    int tid = threadIdx.x;
    size_t base = (size_t)blockIdx.x * (128 * 64);

    const float4* in4 = (const float4*)(in + base);
#pragma unroll
    for (int i = 0; i < 8; i++) {
        int idx = tid + i * 256;
        int node = idx >> 4, c4 = idx & 15;
        float4 v = in4[idx];
        *(float4*)&insm[node][c4 * 4] = v;
    }
    const float4* w4p = (const float4*)Wm;
#pragma unroll
    for (int i = 0; i < 4; i++) {
        int idx = tid + i * 256;
        int co = idx >> 4, c4 = idx & 15;
        float4 v = w4p[idx];
        ws[c4 * 4 + 0][co] = v.x;
        ws[c4 * 4 + 1][co] = v.y;
        ws[c4 * 4 + 2][co] = v.z;
        ws[c4 * 4 + 3][co] = v.w;
    }
    if (tid < 64) bsm[tid] = bias ? bias[tid] : 0.f;
    __syncthreads();

    int tx = tid & 15, ty = tid >> 4;
    int co0 = tx * 4, n0 = ty * 8;
    float acc[8][4];
#pragma unroll
    for (int i = 0; i < 8; i++) {
        acc[i][0] = bsm[co0]; acc[i][1] = bsm[co0 + 1];
        acc[i][2] = bsm[co0 + 2]; acc[i][3] = bsm[co0 + 3];
    }
#pragma unroll 8
    for (int ci = 0; ci < 64; ci++) {
        float4 w = *(const float4*)&ws[ci][co0];
#pragma unroll
        for (int i = 0; i < 8; i++) {
            float a = insm[n0 + i][ci];
            acc[i][0] += a * w.x; acc[i][1] += a * w.y;
            acc[i][2] += a * w.z; acc[i][3] += a * w.w;
        }
    }
#pragma unroll
    for (int i = 0; i < 8; i++)
        *(float4*)&out[base + (size_t)(n0 + i) * 64 + co0] =
            make_float4(acc[i][0], acc[i][1], acc[i][2], acc[i][3]);
}

// ---------------- gcn: dinv + self-loop init of accumulator ----------------
__global__ void k_gcn_init() {
    int gid = blockIdx.x * blockDim.x + threadIdx.x;  // NN*16 threads
    int i = gid >> 4, qd = gid & 15;
    float d = g_deg[i];
    if (qd == 0) g_dinv[i] = rsqrtf(d);
    float s = 2.0f / d;
    float4 h4 = ((const float4*)g_hw)[(size_t)i * 16 + qd];
    ((float4*)g_acc)[(size_t)i * 16 + qd] = make_float4(s * h4.x, s * h4.y, s * h4.z, s * h4.w);
}

// ---------------- gcn edge scatter ----------------
__global__ void k_gcn_scatter(const int* __restrict__ ei, const float* __restrict__ ew) {
    int gid = blockIdx.x * blockDim.x + threadIdx.x;  // EE*16 threads
    int e = gid >> 4, qd = gid & 15;
    int r = ei[e], c = ei[EE + e];
    float coeff = g_dinv[r] * g_dinv[c] * ew[2 * e + 1];
    float4 h4 = ((const float4*)g_hw)[(size_t)r * 16 + qd];
    redAdd4(g_acc + (size_t)c * 64 + qd * 4,
            coeff * h4.x, coeff * h4.y, coeff * h4.z, coeff * h4.w);
}

// ---------------- gcn finalize: +gcn_b, bn1, elu -> h1 ----------------
__global__ void k_gcn_final(const float* __restrict__ gb,
                            const float* __restrict__ g1, const float* __restrict__ b1,
                            const float* __restrict__ m1, const float* __restrict__ v1) {
    int gid = blockIdx.x * blockDim.x + threadIdx.x;  // NN*16
    int i = gid >> 4, qd = gid & 15;
    float4 a4 = ((const float4*)g_acc)[(size_t)i * 16 + qd];
    int c0 = qd * 4;
    float r[4] = {a4.x, a4.y, a4.z, a4.w};
#pragma unroll
    for (int j = 0; j < 4; j++) {
        int c = c0 + j;
        float val = r[j] + __ldg(&gb[c]);
        float sc = __ldg(&g1[c]) * rsqrtf(__ldg(&v1[c]) + 1e-5f);
        r[j] = eluf((val - __ldg(&m1[c])) * sc + __ldg(&b1[c]));
    }
    ((float4*)g_h1)[(size_t)i * 16 + qd] = make_float4(r[0], r[1], r[2], r[3]);
}

// ---------------- attention alpha + segment max (warp per edge) ----------------
__global__ void k_alpha(const int* __restrict__ ei, const float* __restrict__ ew,
                        const float* __restrict__ we) {
    __shared__ float wesm[128];
    int tid = threadIdx.x;
    if (tid < 128) wesm[tid] = we[tid];
    __syncthreads();
    int e = blockIdx.x * 8 + (tid >> 5);
    int lane = tid & 31;
    int r = ei[e], c = ei[EE + e];
    float2 ewv = ((const float2*)ew)[e];
    float2 q2 = ((const float2*)g_q)[(size_t)c * 32 + lane];
    float2 k2 = ((const float2*)g_k)[(size_t)r * 32 + lane];
    float2 w0 = ((const float2*)wesm)[2 * lane];
    float2 w1 = ((const float2*)wesm)[2 * lane + 1];
    float s = q2.x * (k2.x + w0.x * ewv.x + w0.y * ewv.y)
            + q2.y * (k2.y + w1.x * ewv.x + w1.y * ewv.y);
#pragma unroll
    for (int o = 16; o; o >>= 1) s += __shfl_xor_sync(0xffffffffu, s, o);
    if (lane == 0) {
        s *= 0.125f;  // 1/sqrt(64)
        g_alpha[e] = s;
        atomicMaxF(&g_amax[c], s);
    }
}

// ---------------- ex + denom (thread per edge); overwrites g_alpha with ex ----
__global__ void k_denom(const int* __restrict__ ei) {
    int e = blockIdx.x * blockDim.x + threadIdx.x;
    if (e < EE) {
        int c = ei[EE + e];
        float ex = expf(g_alpha[e] - g_amax[c]);
        g_alpha[e] = ex;
        atomicAdd(&g_denom[c], ex);
    }
}

// ---------------- message scatter: acc2[col] += (v[row]+e)*attn --------------
__global__ void k_msg(const int* __restrict__ ei, const float* __restrict__ ew,
                      const float* __restrict__ we) {
    __shared__ float wesm[128];
    int tid = threadIdx.x;
    if (tid < 128) wesm[tid] = we[tid];
    __syncthreads();
    int gid = blockIdx.x * 256 + tid;  // EE*16 threads
    int e = gid >> 4, qd = gid & 15;
    int r = ei[e], c = ei[EE + e];
    float2 ewv = ((const float2*)ew)[e];
    float attn = g_alpha[e] / g_denom[c];
    float4 v4 = ((const float4*)g_v)[(size_t)r * 16 + qd];
    int c0 = qd * 4;
    float m0 = (v4.x + wesm[2 * c0 + 0] * ewv.x + wesm[2 * c0 + 1] * ewv.y) * attn;
    float m1 = (v4.y + wesm[2 * c0 + 2] * ewv.x + wesm[2 * c0 + 3] * ewv.y) * attn;
    float m2 = (v4.z + wesm[2 * c0 + 4] * ewv.x + wesm[2 * c0 + 5] * ewv.y) * attn;
    float m3 = (v4.w + wesm[2 * c0 + 6] * ewv.x + wesm[2 * c0 + 7] * ewv.y) * attn;
    redAdd4(g_acc2 + (size_t)c * 64 + c0, m0, m1, m2, m3);
}

// ---------------- final: bn1(acc2) @ wl.T + bl (warp per node) ---------------
__global__ void k_final(const float* __restrict__ g1, const float* __restrict__ b1,
                        const float* __restrict__ m1, const float* __restrict__ v1,
                        const float* __restrict__ wl, const float* __restrict__ bl,
                        float* __restrict__ out) {
    int t = blockIdx.x * blockDim.x + threadIdx.x;  // NN*32 threads
    int node = t >> 5, lane = t & 31;
    float2 a2 = ((const float2*)g_acc2)[(size_t)node * 32 + lane];
    int c0 = lane * 2;
    float s0 = __ldg(&g1[c0]) * rsqrtf(__ldg(&v1[c0]) + 1e-5f);
    float s1 = __ldg(&g1[c0 + 1]) * rsqrtf(__ldg(&v1[c0 + 1]) + 1e-5f);
    float x0 = (a2.x - __ldg(&m1[c0])) * s0 + __ldg(&b1[c0]);
    float x1 = (a2.y - __ldg(&m1[c0 + 1])) * s1 + __ldg(&b1[c0 + 1]);
    float s = x0 * __ldg(&wl[c0]) + x1 * __ldg(&wl[c0 + 1]);
#pragma unroll
    for (int o = 16; o; o >>= 1) s += __shfl_xor_sync(0xffffffffu, s, o);
    if (lane == 0) out[node] = s + __ldg(&bl[0]);
}

// ---------------- host launcher ----------------
extern "C" void kernel_launch(void* const* d_in, const int* in_sizes, int n_in,
                              void* d_out, int out_size) {
    (void)in_sizes; (void)n_in; (void)out_size;
    const float* x     = (const float*)d_in[0];
    const int*   ei    = (const int*)d_in[1];
    const float* ew    = (const float*)d_in[2];
    const float* cw    = (const float*)d_in[6];
    const float* bn2g  = (const float*)d_in[7];
    const float* bn2b  = (const float*)d_in[8];
    const float* bn2m  = (const float*)d_in[9];
    const float* bn2v  = (const float*)d_in[10];
    const float* gcnw  = (const float*)d_in[11];
    const float* gcnb  = (const float*)d_in[12];
    const float* bn1g  = (const float*)d_in[13];
    const float* bn1b  = (const float*)d_in[14];
    const float* bn1m  = (const float*)d_in[15];
    const float* bn1v  = (const float*)d_in[16];
    const float* wq    = (const float*)d_in[17];
    const float* bq    = (const float*)d_in[18];
    const float* wk    = (const float*)d_in[19];
    const float* bk    = (const float*)d_in[20];
    const float* wv    = (const float*)d_in[21];
    const float* bv    = (const float*)d_in[22];
    const float* we    = (const float*)d_in[23];
    const float* wsk   = (const float*)d_in[24];
    const float* bsk   = (const float*)d_in[25];
    const float* wl    = (const float*)d_in[26];
    const float* bl    = (const float*)d_in[27];

    float *p_h0, *p_hw, *p_h1, *p_q, *p_k, *p_v, *p_acc2;
    cudaGetSymbolAddress((void**)&p_h0,   g_h0);
    cudaGetSymbolAddress((void**)&p_hw,   g_hw);
    cudaGetSymbolAddress((void**)&p_h1,   g_h1);
    cudaGetSymbolAddress((void**)&p_q,    g_q);
    cudaGetSymbolAddress((void**)&p_k,    g_k);
    cudaGetSymbolAddress((void**)&p_v,    g_v);
    cudaGetSymbolAddress((void**)&p_acc2, g_acc2);

    const int conv_smem = (18432 + 32 * 204) * 4;
    cudaFuncSetAttribute(k_conv, cudaFuncAttributeMaxDynamicSharedMemorySize, conv_smem);

    k_init<<<NN / 256, 256>>>();
    k_deg<<<EE / 256, 256>>>(ei, ew);
    k_conv<<<2048, 256, conv_smem>>>(x, cw, bn2g, bn2b, bn2m, bn2v);
    k_gemm<<<NN / 128, 256>>>(p_h0, gcnw, nullptr, p_hw);
    k_gcn_init<<<NN * 16 / 256, 256>>>();
    k_gcn_scatter<<<EE * 16 / 256, 256>>>(ei, ew);
    k_gcn_final<<<NN * 16 / 256, 256>>>(gcnb, bn1g, bn1b, bn1m, bn1v);
    k_gemm<<<NN / 128, 256>>>(p_h1, wq, bq, p_q);
    k_gemm<<<NN / 128, 256>>>(p_h1, wk, bk, p_k);
    k_gemm<<<NN / 128, 256>>>(p_h1, wv, bv, p_v);
    k_gemm<<<NN / 128, 256>>>(p_h1, wsk, bsk, p_acc2);
    k_alpha<<<EE / 8, 256>>>(ei, ew, we);
    k_denom<<<EE / 256, 256>>>(ei);
    k_msg<<<EE * 16 / 256, 256>>>(ei, ew, we);
    k_final<<<NN * 32 / 256, 256>>>(bn1g, bn1b, bn1m, bn1v, wl, bl, (float*)d_out);
}

// round 5
// speedup vs baseline: 2.1132x; 1.2095x over previous
#include <cuda_runtime.h>
#include <math.h>

#define NN 131072
#define EE 1048576
#define HH 256
#define WW 256

typedef unsigned long long ull;

// ---------------- scratch (device globals; no allocations) ----------------
__device__ __align__(16) float g_h0[NN * 64];    // conv+bn2+elu output
__device__ __align__(16) float g_hw[NN * 64];    // h0 @ gcn_w.T
__device__ __align__(16) float g_q[NN * 64];
__device__ __align__(16) float g_k[NN * 64];
__device__ __align__(16) float g_v[NN * 64];
__device__ __align__(16) float g_acc[NN * 64];   // gcn aggregation accumulator
__device__ __align__(16) float g_acc2[NN * 64];  // skip + attention messages
__device__ __align__(16) float g_deg[NN];
__device__ __align__(16) float g_dinv[NN];
__device__ __align__(16) float g_amax[NN];
__device__ __align__(16) float g_denom[NN];
__device__ __align__(16) float g_alpha[EE];      // alpha, then overwritten with ex

__device__ __forceinline__ float eluf(float x) {
    return x > 0.f ? x : 0.1f * expm1f(x);
}
__device__ __forceinline__ void atomicMaxF(float* addr, float val) {
    if (val >= 0.f) atomicMax((int*)addr, __float_as_int(val));
    else            atomicMin((unsigned int*)addr, __float_as_uint(val));
}
__device__ __forceinline__ void redAdd4(float* dst, float a, float b, float c, float d) {
    asm volatile("red.global.add.v4.f32 [%0], {%1,%2,%3,%4};"
                 :: "l"(dst), "f"(a), "f"(b), "f"(c), "f"(d) : "memory");
}
// packed fp32x2 FMA (FFMA2) — 2x fp32 throughput, PTX-only
__device__ __forceinline__ void fma2(ull& acc, ull a, ull w) {
    asm("fma.rn.f32x2 %0, %1, %2, %0;" : "+l"(acc) : "l"(a), "l"(w));
}
__device__ __forceinline__ ull dup2(float a) {
    ull r; asm("mov.b64 %0, {%1, %1};" : "=l"(r) : "f"(a)); return r;
}
__device__ __forceinline__ float2 unpack2(ull v) {
    float2 r; asm("mov.b64 {%0, %1}, %2;" : "=f"(r.x), "=f"(r.y) : "l"(v)); return r;
}

// ---------------- init ----------------
__global__ void k_init() {
    int i = blockIdx.x * blockDim.x + threadIdx.x;
    if (i < NN) {
        g_deg[i]   = 2.0f;
        g_amax[i]  = -INFINITY;
        g_denom[i] = 0.0f;
    }
}
__global__ void k_deg(const int* __restrict__ ei, const float* __restrict__ ew) {
    int e = blockIdx.x * blockDim.x + threadIdx.x;
    if (e < EE) atomicAdd(&g_deg[ei[EE + e]], ew[2 * e + 1]);
}
__global__ void k_dinv() {
    int i = blockIdx.x * blockDim.x + threadIdx.x;
    if (i < NN) g_dinv[i] = rsqrtf(g_deg[i]);
}

// ---------------- conv 3x3 SAME + bn2 + elu (FFMA2, kx register reuse) -------
// 256 threads: tx=tid&15 -> co0=tx*4 (64 co); ty=tid>>4 in [0,15] -> px0=ty*4 (64 px)
__global__ void __launch_bounds__(256, 2)
k_conv(const float* __restrict__ x, const float* __restrict__ cw,
       const float* __restrict__ bg, const float* __restrict__ bb,
       const float* __restrict__ bm, const float* __restrict__ bv) {
    extern __shared__ float sm[];
    float* ws  = sm;            // [k][ci][co] : 9*32*64
    float* ins = sm + 18432;    // [ci][r][px] : 32 * 3*68

    int tid = threadIdx.x;
    int bid = blockIdx.x;
    int xt = bid & 3;
    int y  = (bid >> 2) & 255;
    int b  = bid >> 10;
    int x0 = xt * 64;

    for (int i = tid; i < 18432; i += 256) {
        int co = i & 63;
        int ci = (i >> 6) & 31;
        int kk = i >> 11;
        int ky = kk / 3, kx = kk - ky * 3;
        ws[i] = cw[((co * 32 + ci) * 3 + ky) * 3 + kx];
    }
    for (int i = tid; i < 3 * 66 * 32; i += 256) {
        int ci = i & 31;
        int p  = i >> 5;
        int r  = p / 66;
        int px = p - r * 66;
        int yy = y + r - 1;
        int xx = x0 + px - 1;
        float val = 0.f;
        if (yy >= 0 && yy < HH && xx >= 0 && xx < WW)
            val = x[(((size_t)b * HH + yy) * WW + xx) * 32 + ci];
        ins[ci * 204 + r * 68 + px] = val;
    }
    __syncthreads();

    int tx = tid & 15;   // co group
    int ty = tid >> 4;   // px group in [0,15]
    int co0 = tx * 4;
    int px0 = ty * 4;

    ull acc[4][2];
#pragma unroll
    for (int i = 0; i < 4; i++) { acc[i][0] = 0ull; acc[i][1] = 0ull; }

#pragma unroll
    for (int ky = 0; ky < 3; ky++) {
        const float* ipk = ins + ky * 68 + px0;
#pragma unroll 4
        for (int ci = 0; ci < 32; ci++) {
            const float* ip = ipk + ci * 204;
            float4 al = *(const float4*)ip;
            float2 ah = *(const float2*)(ip + 4);
            ull a[6];
            a[0] = dup2(al.x); a[1] = dup2(al.y); a[2] = dup2(al.z);
            a[3] = dup2(al.w); a[4] = dup2(ah.x); a[5] = dup2(ah.y);
#pragma unroll
            for (int kx = 0; kx < 3; kx++) {
                ulonglong2 w = *(const ulonglong2*)&ws[((ky * 3 + kx) * 32 + ci) * 64 + co0];
                fma2(acc[0][0], a[kx + 0], w.x); fma2(acc[0][1], a[kx + 0], w.y);
                fma2(acc[1][0], a[kx + 1], w.x); fma2(acc[1][1], a[kx + 1], w.y);
                fma2(acc[2][0], a[kx + 2], w.x); fma2(acc[2][1], a[kx + 2], w.y);
                fma2(acc[3][0], a[kx + 3], w.x); fma2(acc[3][1], a[kx + 3], w.y);
            }
        }
    }

    float sc[4], mm[4], bbv[4];
#pragma unroll
    for (int j = 0; j < 4; j++) {
        int c = co0 + j;
        sc[j]  = __ldg(&bg[c]) * rsqrtf(__ldg(&bv[c]) + 1e-5f);
        mm[j]  = __ldg(&bm[c]);
        bbv[j] = __ldg(&bb[c]);
    }
    size_t pixbase = ((size_t)b * HH + y) * WW + x0 + px0;
#pragma unroll
    for (int i = 0; i < 4; i++) {
        float2 p0 = unpack2(acc[i][0]);
        float2 p1 = unpack2(acc[i][1]);
        float r0 = eluf((p0.x - mm[0]) * sc[0] + bbv[0]);
        float r1 = eluf((p0.y - mm[1]) * sc[1] + bbv[1]);
        float r2 = eluf((p1.x - mm[2]) * sc[2] + bbv[2]);
        float r3 = eluf((p1.y - mm[3]) * sc[3] + bbv[3]);
        *(float4*)(g_h0 + (pixbase + i) * 64 + co0) = make_float4(r0, r1, r2, r3);
    }
}

// ---------------- gemm1: hw = h0 @ gcn_w.T; also g_acc = (2/deg)*hw ---------
// 256 threads: tx=tid&7 -> co0=tx*8 (64 co); ty=tid>>3 in [0,31] -> n0=ty*8 (256 rows)
__global__ void __launch_bounds__(256)
k_gemm1(const float* __restrict__ in, const float* __restrict__ Wm) {
    extern __shared__ float sm[];
    float* sA = sm;               // [256][65]
    float* sW = sm + 256 * 65;    // [64][68]

    int tid = threadIdx.x;
    size_t base = (size_t)blockIdx.x * 256;

    const float4* src = (const float4*)(in + base * 64);
#pragma unroll
    for (int i = 0; i < 16; i++) {
        int idx = tid + i * 256;               // 0..4095
        int node = idx >> 4, c4 = idx & 15;
        float4 v = src[idx];
        float* dst = &sA[node * 65 + c4 * 4];
        dst[0] = v.x; dst[1] = v.y; dst[2] = v.z; dst[3] = v.w;
    }
    const float4* w4 = (const float4*)Wm;
#pragma unroll
    for (int i = 0; i < 4; i++) {
        int idx = tid + i * 256;               // 0..1023
        int co = idx >> 4, c4 = idx & 15;
        float4 v = w4[idx];
        sW[(c4 * 4 + 0) * 68 + co] = v.x;
        sW[(c4 * 4 + 1) * 68 + co] = v.y;
        sW[(c4 * 4 + 2) * 68 + co] = v.z;
        sW[(c4 * 4 + 3) * 68 + co] = v.w;
    }
    __syncthreads();

    int tx = tid & 7, ty = tid >> 3;   // tx in [0,7], ty in [0,31]
    int co0 = tx * 8, n0 = ty * 8;

    ull acc[8][4];
#pragma unroll
    for (int i = 0; i < 8; i++)
#pragma unroll
        for (int j = 0; j < 4; j++) acc[i][j] = 0ull;

    for (int ci = 0; ci < 64; ci++) {
        ulonglong2 w01 = *(const ulonglong2*)&sW[ci * 68 + co0];
        ulonglong2 w23 = *(const ulonglong2*)&sW[ci * 68 + co0 + 4];
        const float* ap = &sA[n0 * 65 + ci];
#pragma unroll
        for (int i = 0; i < 8; i++) {
            ull a = dup2(ap[i * 65]);
            fma2(acc[i][0], a, w01.x); fma2(acc[i][1], a, w01.y);
            fma2(acc[i][2], a, w23.x); fma2(acc[i][3], a, w23.y);
        }
    }
#pragma unroll
    for (int i = 0; i < 8; i++) {
        size_t node = base + n0 + i;
        float s = 2.0f / g_deg[node];
        float2 p0 = unpack2(acc[i][0]), p1 = unpack2(acc[i][1]);
        float2 p2 = unpack2(acc[i][2]), p3 = unpack2(acc[i][3]);
        float4 v0 = make_float4(p0.x, p0.y, p1.x, p1.y);
        float4 v1 = make_float4(p2.x, p2.y, p3.x, p3.y);
        *(float4*)(g_hw + node * 64 + co0)     = v0;
        *(float4*)(g_hw + node * 64 + co0 + 4) = v1;
        *(float4*)(g_acc + node * 64 + co0)     = make_float4(s * v0.x, s * v0.y, s * v0.z, s * v0.w);
        *(float4*)(g_acc + node * 64 + co0 + 4) = make_float4(s * v1.x, s * v1.y, s * v1.z, s * v1.w);
    }
}

// ---------------- gemm4: q,k,v,skip from elu(bn1(acc+gcn_b)) -----------------
// 256 threads, same 8x8 micro mapping as gemm1.
__global__ void __launch_bounds__(256)
k_gemm4(const float* __restrict__ gb,
        const float* __restrict__ g1, const float* __restrict__ b1,
        const float* __restrict__ m1, const float* __restrict__ v1,
        const float* __restrict__ W0, const float* __restrict__ W1,
        const float* __restrict__ W2, const float* __restrict__ W3,
        const float* __restrict__ bb0, const float* __restrict__ bb1,
        const float* __restrict__ bb2, const float* __restrict__ bb3,
        float* __restrict__ O0, float* __restrict__ O1,
        float* __restrict__ O2, float* __restrict__ O3) {
    extern __shared__ float sm[];
    float* sA  = sm;                       // [256][65] = 16640
    float* sW  = sm + 16640;               // [4][64][68] = 17408
    float* bs  = sm + 16640 + 17408;       // [4][64]
    float* pSc = bs + 256;                 // [64]
    float* pOf = pSc + 64;                 // [64]

    int tid = threadIdx.x;
    size_t base = (size_t)blockIdx.x * 256;

    if (tid < 64) {
        float scv = __ldg(&g1[tid]) * rsqrtf(__ldg(&v1[tid]) + 1e-5f);
        pSc[tid] = scv;
        pOf[tid] = (__ldg(&gb[tid]) - __ldg(&m1[tid])) * scv + __ldg(&b1[tid]);
        bs[tid]       = __ldg(&bb0[tid]);
        bs[64 + tid]  = __ldg(&bb1[tid]);
        bs[128 + tid] = __ldg(&bb2[tid]);
        bs[192 + tid] = __ldg(&bb3[tid]);
    }
    __syncthreads();

    const float4* src = (const float4*)(g_acc + base * 64);
#pragma unroll
    for (int i = 0; i < 16; i++) {
        int idx = tid + i * 256;               // 0..4095
        int node = idx >> 4, c4 = idx & 15;
        int c = c4 * 4;
        float4 v = src[idx];
        float* dst = &sA[node * 65 + c];
        dst[0] = eluf(v.x * pSc[c]     + pOf[c]);
        dst[1] = eluf(v.y * pSc[c + 1] + pOf[c + 1]);
        dst[2] = eluf(v.z * pSc[c + 2] + pOf[c + 2]);
        dst[3] = eluf(v.w * pSc[c + 3] + pOf[c + 3]);
    }
    const float* Wsrc[4] = {W0, W1, W2, W3};
#pragma unroll
    for (int m = 0; m < 4; m++) {
        const float4* w4 = (const float4*)Wsrc[m];
#pragma unroll
        for (int i = 0; i < 4; i++) {
            int idx = tid + i * 256;           // 0..1023
            int co = idx >> 4, c4 = idx & 15;
            float4 v = w4[idx];
            float* wb = sW + m * 4352;
            wb[(c4 * 4 + 0) * 68 + co] = v.x;
            wb[(c4 * 4 + 1) * 68 + co] = v.y;
            wb[(c4 * 4 + 2) * 68 + co] = v.z;
            wb[(c4 * 4 + 3) * 68 + co] = v.w;
        }
    }
    __syncthreads();

    int tx = tid & 7, ty = tid >> 3;   // tx in [0,7], ty in [0,31]
    int co0 = tx * 8, n0 = ty * 8;
    float* Odst[4] = {O0, O1, O2, O3};

#pragma unroll
    for (int m = 0; m < 4; m++) {
        const float* wb = sW + m * 4352;
        ulonglong2 bi0 = *(const ulonglong2*)&bs[m * 64 + co0];
        ulonglong2 bi1 = *(const ulonglong2*)&bs[m * 64 + co0 + 4];
        ull acc[8][4];
#pragma unroll
        for (int i = 0; i < 8; i++) {
            acc[i][0] = bi0.x; acc[i][1] = bi0.y;
            acc[i][2] = bi1.x; acc[i][3] = bi1.y;
        }
        for (int ci = 0; ci < 64; ci++) {
            ulonglong2 w01 = *(const ulonglong2*)&wb[ci * 68 + co0];
            ulonglong2 w23 = *(const ulonglong2*)&wb[ci * 68 + co0 + 4];
            const float* ap = &sA[n0 * 65 + ci];
#pragma unroll
            for (int i = 0; i < 8; i++) {
                ull a = dup2(ap[i * 65]);
                fma2(acc[i][0], a, w01.x); fma2(acc[i][1], a, w01.y);
                fma2(acc[i][2], a, w23.x); fma2(acc[i][3], a, w23.y);
            }
        }
        float* out = Odst[m];
#pragma unroll
        for (int i = 0; i < 8; i++) {
            size_t node = base + n0 + i;
            float2 p0 = unpack2(acc[i][0]), p1 = unpack2(acc[i][1]);
            float2 p2 = unpack2(acc[i][2]), p3 = unpack2(acc[i][3]);
            *(float4*)(out + node * 64 + co0)     = make_float4(p0.x, p0.y, p1.x, p1.y);
            *(float4*)(out + node * 64 + co0 + 4) = make_float4(p2.x, p2.y, p3.x, p3.y);
        }
    }
}

// ---------------- gcn edge scatter ----------------
__global__ void k_gcn_scatter(const int* __restrict__ ei, const float* __restrict__ ew) {
    int gid = blockIdx.x * blockDim.x + threadIdx.x;  // EE*16
    int e = gid >> 4, qd = gid & 15;
    int r = ei[e], c = ei[EE + e];
    float coeff = g_dinv[r] * g_dinv[c] * ew[2 * e + 1];
    float4 h4 = ((const float4*)g_hw)[(size_t)r * 16 + qd];
    redAdd4(g_acc + (size_t)c * 64 + qd * 4,
            coeff * h4.x, coeff * h4.y, coeff * h4.z, coeff * h4.w);
}

// ---------------- attention alpha + segment max (16 lanes per edge) ----------
__global__ void k_alpha(const int* __restrict__ ei, const float* __restrict__ ew,
                        const float* __restrict__ we) {
    __shared__ float4 wesm4[32];
    int tid = threadIdx.x;
    if (tid < 32) wesm4[tid] = ((const float4*)we)[tid];
    __syncthreads();
    int gid = blockIdx.x * 256 + tid;   // EE*16
    int e = gid >> 4;
    int l = gid & 15;
    int r = ei[e], c = ei[EE + e];
    float2 ewv = ((const float2*)ew)[e];
    float4 q4 = ((const float4*)g_q)[(size_t)c * 16 + l];
    float4 k4 = ((const float4*)g_k)[(size_t)r * 16 + l];
    float4 wa = wesm4[l * 2];
    float4 wb = wesm4[l * 2 + 1];
    float s = q4.x * (k4.x + wa.x * ewv.x + wa.y * ewv.y)
            + q4.y * (k4.y + wa.z * ewv.x + wa.w * ewv.y)
            + q4.z * (k4.z + wb.x * ewv.x + wb.y * ewv.y)
            + q4.w * (k4.w + wb.z * ewv.x + wb.w * ewv.y);
    s += __shfl_xor_sync(0xffffffffu, s, 8);
    s += __shfl_xor_sync(0xffffffffu, s, 4);
    s += __shfl_xor_sync(0xffffffffu, s, 2);
    s += __shfl_xor_sync(0xffffffffu, s, 1);
    if (l == 0) {
        s *= 0.125f;
        g_alpha[e] = s;
        atomicMaxF(&g_amax[c], s);
    }
}

// ---------------- ex + denom ----------------
__global__ void k_denom(const int* __restrict__ ei) {
    int e = blockIdx.x * blockDim.x + threadIdx.x;
    if (e < EE) {
        int c = ei[EE + e];
        float ex = expf(g_alpha[e] - g_amax[c]);
        g_alpha[e] = ex;
        atomicAdd(&g_denom[c], ex);
    }
}

// ---------------- message scatter ----------------
__global__ void k_msg(const int* __restrict__ ei, const float* __restrict__ ew,
                      const float* __restrict__ we) {
    __shared__ float wesm[128];
    int tid = threadIdx.x;
    if (tid < 128) wesm[tid] = we[tid];
    __syncthreads();
    int gid = blockIdx.x * 256 + tid;  // EE*16
    int e = gid >> 4, qd = gid & 15;
    int r = ei[e], c = ei[EE + e];
    float2 ewv = ((const float2*)ew)[e];
    float attn = g_alpha[e] / g_denom[c];
    float4 v4 = ((const float4*)g_v)[(size_t)r * 16 + qd];
    int c0 = qd * 4;
    float m0 = (v4.x + wesm[2 * c0 + 0] * ewv.x + wesm[2 * c0 + 1] * ewv.y) * attn;
    float m1 = (v4.y + wesm[2 * c0 + 2] * ewv.x + wesm[2 * c0 + 3] * ewv.y) * attn;
    float m2 = (v4.z + wesm[2 * c0 + 4] * ewv.x + wesm[2 * c0 + 5] * ewv.y) * attn;
    float m3 = (v4.w + wesm[2 * c0 + 6] * ewv.x + wesm[2 * c0 + 7] * ewv.y) * attn;
    redAdd4(g_acc2 + (size_t)c * 64 + c0, m0, m1, m2, m3);
}

// ---------------- final: bn1(acc2) @ wl.T + bl (warp per node) ---------------
__global__ void k_final(const float* __restrict__ g1, const float* __restrict__ b1,
                        const float* __restrict__ m1, const float* __restrict__ v1,
                        const float* __restrict__ wl, const float* __restrict__ bl,
                        float* __restrict__ out) {
    int t = blockIdx.x * blockDim.x + threadIdx.x;  // NN*32
    int node = t >> 5, lane = t & 31;
    float2 a2 = ((const float2*)g_acc2)[(size_t)node * 32 + lane];
    int c0 = lane * 2;
    float s0 = __ldg(&g1[c0]) * rsqrtf(__ldg(&v1[c0]) + 1e-5f);
    float s1 = __ldg(&g1[c0 + 1]) * rsqrtf(__ldg(&v1[c0 + 1]) + 1e-5f);
    float x0 = (a2.x - __ldg(&m1[c0])) * s0 + __ldg(&b1[c0]);
    float x1 = (a2.y - __ldg(&m1[c0 + 1])) * s1 + __ldg(&b1[c0 + 1]);
    float s = x0 * __ldg(&wl[c0]) + x1 * __ldg(&wl[c0 + 1]);
#pragma unroll
    for (int o = 16; o; o >>= 1) s += __shfl_xor_sync(0xffffffffu, s, o);
    if (lane == 0) out[node] = s + __ldg(&bl[0]);
}

// ---------------- host launcher ----------------
extern "C" void kernel_launch(void* const* d_in, const int* in_sizes, int n_in,
                              void* d_out, int out_size) {
    (void)in_sizes; (void)n_in; (void)out_size;
    const float* x     = (const float*)d_in[0];
    const int*   ei    = (const int*)d_in[1];
    const float* ew    = (const float*)d_in[2];
    const float* cw    = (const float*)d_in[6];
    const float* bn2g  = (const float*)d_in[7];
    const float* bn2b  = (const float*)d_in[8];
    const float* bn2m  = (const float*)d_in[9];
    const float* bn2v  = (const float*)d_in[10];
    const float* gcnw  = (const float*)d_in[11];
    const float* gcnb  = (const float*)d_in[12];
    const float* bn1g  = (const float*)d_in[13];
    const float* bn1b  = (const float*)d_in[14];
    const float* bn1m  = (const float*)d_in[15];
    const float* bn1v  = (const float*)d_in[16];
    const float* wq    = (const float*)d_in[17];
    const float* bq    = (const float*)d_in[18];
    const float* wk    = (const float*)d_in[19];
    const float* bk    = (const float*)d_in[20];
    const float* wv    = (const float*)d_in[21];
    const float* bv    = (const float*)d_in[22];
    const float* we    = (const float*)d_in[23];
    const float* wsk   = (const float*)d_in[24];
    const float* bsk   = (const float*)d_in[25];
    const float* wl    = (const float*)d_in[26];
    const float* bl    = (const float*)d_in[27];

    float *p_h0, *p_q, *p_k, *p_v, *p_acc2;
    cudaGetSymbolAddress((void**)&p_h0,   g_h0);
    cudaGetSymbolAddress((void**)&p_q,    g_q);
    cudaGetSymbolAddress((void**)&p_k,    g_k);
    cudaGetSymbolAddress((void**)&p_v,    g_v);
    cudaGetSymbolAddress((void**)&p_acc2, g_acc2);

    const int conv_smem  = (18432 + 32 * 204) * 4;
    const int gemm1_smem = (256 * 65 + 64 * 68) * 4;
    const int gemm4_smem = (256 * 65 + 4 * 64 * 68 + 256 + 128) * 4;
    cudaFuncSetAttribute(k_conv,  cudaFuncAttributeMaxDynamicSharedMemorySize, conv_smem);
    cudaFuncSetAttribute(k_gemm1, cudaFuncAttributeMaxDynamicSharedMemorySize, gemm1_smem);
    cudaFuncSetAttribute(k_gemm4, cudaFuncAttributeMaxDynamicSharedMemorySize, gemm4_smem);

    k_init<<<NN / 256, 256>>>();
    k_deg<<<EE / 256, 256>>>(ei, ew);
    k_dinv<<<NN / 256, 256>>>();
    k_conv<<<2048, 256, conv_smem>>>(x, cw, bn2g, bn2b, bn2m, bn2v);
    k_gemm1<<<NN / 256, 256, gemm1_smem>>>(p_h0, gcnw);
    k_gcn_scatter<<<EE * 16 / 256, 256>>>(ei, ew);
    k_gemm4<<<NN / 256, 256, gemm4_smem>>>(gcnb, bn1g, bn1b, bn1m, bn1v,
                                           wq, wk, wv, wsk, bq, bk, bv, bsk,
                                           p_q, p_k, p_v, p_acc2);
    k_alpha<<<EE * 16 / 256, 256>>>(ei, ew, we);
    k_denom<<<EE / 256, 256>>>(ei);
    k_msg<<<EE * 16 / 256, 256>>>(ei, ew, we);
    k_final<<<NN * 32 / 256, 256>>>(bn1g, bn1b, bn1m, bn1v, wl, bl, (float*)d_out);
}

// round 6
// speedup vs baseline: 2.7860x; 1.3184x over previous
#include <cuda_runtime.h>
#include <math.h>

#define NN 131072
#define EE 1048576
#define HH 256
#define WW 256

typedef unsigned long long ull;

// ---------------- scratch (device globals; no allocations) ----------------
__device__ __align__(16) float g_h0[NN * 64];    // conv+bn2+elu output
__device__ __align__(16) float g_hw[NN * 64];    // h0 @ gcn_w.T
__device__ __align__(16) float g_q[NN * 64];
__device__ __align__(16) float g_k[NN * 64];
__device__ __align__(16) float g_v[NN * 64];
__device__ __align__(16) float g_acc[NN * 64];   // gcn aggregation accumulator
__device__ __align__(16) float g_acc2[NN * 64];  // skip + attention messages
__device__ __align__(16) float g_deg[NN];
__device__ __align__(16) float g_dinv[NN];
__device__ __align__(16) float g_amax[NN];
__device__ __align__(16) float g_denom[NN];
__device__ __align__(16) float g_alpha[EE];      // alpha, then overwritten with ex
__device__ __align__(16) float g_wT[9 * 32 * 64]; // conv weights [k][ci][co]

__device__ __forceinline__ float eluf(float x) {
    return x > 0.f ? x : 0.1f * expm1f(x);
}
__device__ __forceinline__ void atomicMaxF(float* addr, float val) {
    if (val >= 0.f) atomicMax((int*)addr, __float_as_int(val));
    else            atomicMin((unsigned int*)addr, __float_as_uint(val));
}
__device__ __forceinline__ void redAdd4(float* dst, float a, float b, float c, float d) {
    asm volatile("red.global.add.v4.f32 [%0], {%1,%2,%3,%4};"
                 :: "l"(dst), "f"(a), "f"(b), "f"(c), "f"(d) : "memory");
}
// packed fp32x2 FMA (FFMA2) — 2x fp32 throughput, PTX-only
__device__ __forceinline__ void fma2(ull& acc, ull a, ull w) {
    asm("fma.rn.f32x2 %0, %1, %2, %0;" : "+l"(acc) : "l"(a), "l"(w));
}
__device__ __forceinline__ ull dup2(float a) {
    ull r; asm("mov.b64 %0, {%1, %1};" : "=l"(r) : "f"(a)); return r;
}
__device__ __forceinline__ float2 unpack2(ull v) {
    float2 r; asm("mov.b64 {%0, %1}, %2;" : "=f"(r.x), "=f"(r.y) : "l"(v)); return r;
}

// ---------------- init ----------------
__global__ void k_init() {
    int i = blockIdx.x * blockDim.x + threadIdx.x;
    if (i < NN) {
        g_deg[i]   = 2.0f;
        g_amax[i]  = -INFINITY;
        g_denom[i] = 0.0f;
    }
}
__global__ void k_deg(const int* __restrict__ ei, const float* __restrict__ ew) {
    int e = blockIdx.x * blockDim.x + threadIdx.x;
    if (e < EE) atomicAdd(&g_deg[ei[EE + e]], ew[2 * e + 1]);
}
__global__ void k_dinv() {
    int i = blockIdx.x * blockDim.x + threadIdx.x;
    if (i < NN) g_dinv[i] = rsqrtf(g_deg[i]);
}
// transpose conv weights to [k][ci][co] for coalesced staged loads
__global__ void k_wprep(const float* __restrict__ cw) {
    int i = blockIdx.x * blockDim.x + threadIdx.x;   // 18432
    if (i < 18432) {
        int co = i & 63;
        int ci = (i >> 6) & 31;
        int k  = i >> 11;
        int ky = k / 3, kx = k - ky * 3;
        g_wT[i] = cw[((co * 32 + ci) * 3 + ky) * 3 + kx];
    }
}

// ---------------- conv 3x3 SAME + bn2 + elu -----------------------------------
// Double-buffered per-k weight staging: smem = 16KB (w) + 25.5KB (halo) -> 5 CTA/SM
__global__ void __launch_bounds__(256)
k_conv(const float* __restrict__ x,
       const float* __restrict__ bg, const float* __restrict__ bb,
       const float* __restrict__ bm, const float* __restrict__ bv) {
    __shared__ __align__(16) float ins[32 * 204];   // [ci][r][px], r<3, px<68
    __shared__ __align__(16) float wsk[2][2048];    // [buf][ci*64+co]

    int tid = threadIdx.x;
    int bid = blockIdx.x;
    int xt = bid & 3;
    int y  = (bid >> 2) & 255;
    int b  = bid >> 10;
    int x0 = xt * 64;

    // halo load
    for (int i = tid; i < 3 * 66 * 32; i += 256) {
        int ci = i & 31;
        int p  = i >> 5;
        int r  = p / 66;
        int px = p - r * 66;
        int yy = y + r - 1;
        int xx = x0 + px - 1;
        float val = 0.f;
        if (yy >= 0 && yy < HH && xx >= 0 && xx < WW)
            val = x[(((size_t)b * HH + yy) * WW + xx) * 32 + ci];
        ins[ci * 204 + r * 68 + px] = val;
    }
    // stage k=0 weights
    {
        const float4* wsrc = (const float4*)g_wT;
        float4* wdst = (float4*)wsk[0];
#pragma unroll
        for (int i = 0; i < 2; i++) wdst[tid + i * 256] = wsrc[tid + i * 256];
    }
    __syncthreads();

    int tx = tid & 15;   // co group
    int ty = tid >> 4;   // px group in [0,15]
    int co0 = tx * 4;
    int px0 = ty * 4;

    ull acc[4][2];
#pragma unroll
    for (int i = 0; i < 4; i++) { acc[i][0] = 0ull; acc[i][1] = 0ull; }

#pragma unroll
    for (int k = 0; k < 9; k++) {
        int buf = k & 1;
        int ky = k / 3, kx = k - ky * 3;
        const float* ipk = ins + ky * 68 + px0 + kx;
        const float* wb  = wsk[buf] + co0;
#pragma unroll 4
        for (int ci = 0; ci < 32; ci++) {
            const float* ip = ipk + ci * 204;
            float4 av = *(const float4*)(ip - (px0 + kx) % 4 == 0 ? ip : ip);  // plain loads below
            // scalar loads (px0+kx may be unaligned for float4) — use 4 scalar LDS
            float a0 = ip[0], a1 = ip[1], a2 = ip[2], a3 = ip[3];
            (void)av;
            ulonglong2 w = *(const ulonglong2*)(wb + ci * 64);
            ull d0 = dup2(a0), d1 = dup2(a1), d2 = dup2(a2), d3 = dup2(a3);
            fma2(acc[0][0], d0, w.x); fma2(acc[0][1], d0, w.y);
            fma2(acc[1][0], d1, w.x); fma2(acc[1][1], d1, w.y);
            fma2(acc[2][0], d2, w.x); fma2(acc[2][1], d2, w.y);
            fma2(acc[3][0], d3, w.x); fma2(acc[3][1], d3, w.y);
        }
        if (k < 8) {
            const float4* wsrc = (const float4*)(g_wT + (k + 1) * 2048);
            float4* wdst = (float4*)wsk[buf ^ 1];
#pragma unroll
            for (int i = 0; i < 2; i++) wdst[tid + i * 256] = wsrc[tid + i * 256];
        }
        __syncthreads();
    }

    float sc[4], mm[4], bbv[4];
#pragma unroll
    for (int j = 0; j < 4; j++) {
        int c = co0 + j;
        sc[j]  = __ldg(&bg[c]) * rsqrtf(__ldg(&bv[c]) + 1e-5f);
        mm[j]  = __ldg(&bm[c]);
        bbv[j] = __ldg(&bb[c]);
    }
    size_t pixbase = ((size_t)b * HH + y) * WW + x0 + px0;
#pragma unroll
    for (int i = 0; i < 4; i++) {
        float2 p0 = unpack2(acc[i][0]);
        float2 p1 = unpack2(acc[i][1]);
        float r0 = eluf((p0.x - mm[0]) * sc[0] + bbv[0]);
        float r1 = eluf((p0.y - mm[1]) * sc[1] + bbv[1]);
        float r2 = eluf((p1.x - mm[2]) * sc[2] + bbv[2]);
        float r3 = eluf((p1.y - mm[3]) * sc[3] + bbv[3]);
        *(float4*)(g_h0 + (pixbase + i) * 64 + co0) = make_float4(r0, r1, r2, r3);
    }
}

// ---------------- gemm1: hw = h0 @ gcn_w.T; also g_acc = (2/deg)*hw ---------
__global__ void __launch_bounds__(256)
k_gemm1(const float* __restrict__ in, const float* __restrict__ Wm) {
    extern __shared__ float sm[];
    float* sA = sm;               // [256][65]
    float* sW = sm + 256 * 65;    // [64][68]

    int tid = threadIdx.x;
    size_t base = (size_t)blockIdx.x * 256;

    const float4* src = (const float4*)(in + base * 64);
#pragma unroll
    for (int i = 0; i < 16; i++) {
        int idx = tid + i * 256;
        int node = idx >> 4, c4 = idx & 15;
        float4 v = src[idx];
        float* dst = &sA[node * 65 + c4 * 4];
        dst[0] = v.x; dst[1] = v.y; dst[2] = v.z; dst[3] = v.w;
    }
    const float4* w4 = (const float4*)Wm;
#pragma unroll
    for (int i = 0; i < 4; i++) {
        int idx = tid + i * 256;
        int co = idx >> 4, c4 = idx & 15;
        float4 v = w4[idx];
        sW[(c4 * 4 + 0) * 68 + co] = v.x;
        sW[(c4 * 4 + 1) * 68 + co] = v.y;
        sW[(c4 * 4 + 2) * 68 + co] = v.z;
        sW[(c4 * 4 + 3) * 68 + co] = v.w;
    }
    __syncthreads();

    int tx = tid & 7, ty = tid >> 3;
    int co0 = tx * 8, n0 = ty * 8;

    ull acc[8][4];
#pragma unroll
    for (int i = 0; i < 8; i++)
#pragma unroll
        for (int j = 0; j < 4; j++) acc[i][j] = 0ull;

    for (int ci = 0; ci < 64; ci++) {
        ulonglong2 w01 = *(const ulonglong2*)&sW[ci * 68 + co0];
        ulonglong2 w23 = *(const ulonglong2*)&sW[ci * 68 + co0 + 4];
        const float* ap = &sA[n0 * 65 + ci];
#pragma unroll
        for (int i = 0; i < 8; i++) {
            ull a = dup2(ap[i * 65]);
            fma2(acc[i][0], a, w01.x); fma2(acc[i][1], a, w01.y);
            fma2(acc[i][2], a, w23.x); fma2(acc[i][3], a, w23.y);
        }
    }
#pragma unroll
    for (int i = 0; i < 8; i++) {
        size_t node = base + n0 + i;
        float s = 2.0f / g_deg[node];
        float2 p0 = unpack2(acc[i][0]), p1 = unpack2(acc[i][1]);
        float2 p2 = unpack2(acc[i][2]), p3 = unpack2(acc[i][3]);
        float4 v0 = make_float4(p0.x, p0.y, p1.x, p1.y);
        float4 v1 = make_float4(p2.x, p2.y, p3.x, p3.y);
        *(float4*)(g_hw + node * 64 + co0)     = v0;
        *(float4*)(g_hw + node * 64 + co0 + 4) = v1;
        *(float4*)(g_acc + node * 64 + co0)     = make_float4(s * v0.x, s * v0.y, s * v0.z, s * v0.w);
        *(float4*)(g_acc + node * 64 + co0 + 4) = make_float4(s * v1.x, s * v1.y, s * v1.z, s * v1.w);
    }
}

// ---------------- gemm4: q,k,v,skip from elu(bn1(acc+gcn_b)) -----------------
__global__ void __launch_bounds__(256)
k_gemm4(const float* __restrict__ gb,
        const float* __restrict__ g1, const float* __restrict__ b1,
        const float* __restrict__ m1, const float* __restrict__ v1,
        const float* __restrict__ W0, const float* __restrict__ W1,
        const float* __restrict__ W2, const float* __restrict__ W3,
        const float* __restrict__ bb0, const float* __restrict__ bb1,
        const float* __restrict__ bb2, const float* __restrict__ bb3,
        float* __restrict__ O0, float* __restrict__ O1,
        float* __restrict__ O2, float* __restrict__ O3) {
    extern __shared__ float sm[];
    float* sA  = sm;                       // [256][65] = 16640
    float* sW  = sm + 16640;               // [4][64][68] = 17408
    float* bs  = sm + 16640 + 17408;       // [4][64]
    float* pSc = bs + 256;                 // [64]
    float* pOf = pSc + 64;                 // [64]

    int tid = threadIdx.x;
    size_t base = (size_t)blockIdx.x * 256;

    if (tid < 64) {
        float scv = __ldg(&g1[tid]) * rsqrtf(__ldg(&v1[tid]) + 1e-5f);
        pSc[tid] = scv;
        pOf[tid] = (__ldg(&gb[tid]) - __ldg(&m1[tid])) * scv + __ldg(&b1[tid]);
        bs[tid]       = __ldg(&bb0[tid]);
        bs[64 + tid]  = __ldg(&bb1[tid]);
        bs[128 + tid] = __ldg(&bb2[tid]);
        bs[192 + tid] = __ldg(&bb3[tid]);
    }
    __syncthreads();

    const float4* src = (const float4*)(g_acc + base * 64);
#pragma unroll
    for (int i = 0; i < 16; i++) {
        int idx = tid + i * 256;
        int node = idx >> 4, c4 = idx & 15;
        int c = c4 * 4;
        float4 v = src[idx];
        float* dst = &sA[node * 65 + c];
        dst[0] = eluf(v.x * pSc[c]     + pOf[c]);
        dst[1] = eluf(v.y * pSc[c + 1] + pOf[c + 1]);
        dst[2] = eluf(v.z * pSc[c + 2] + pOf[c + 2]);
        dst[3] = eluf(v.w * pSc[c + 3] + pOf[c + 3]);
    }
    const float* Wsrc[4] = {W0, W1, W2, W3};
#pragma unroll
    for (int m = 0; m < 4; m++) {
        const float4* w4 = (const float4*)Wsrc[m];
#pragma unroll
        for (int i = 0; i < 4; i++) {
            int idx = tid + i * 256;
            int co = idx >> 4, c4 = idx & 15;
            float4 v = w4[idx];
            float* wb = sW + m * 4352;
            wb[(c4 * 4 + 0) * 68 + co] = v.x;
            wb[(c4 * 4 + 1) * 68 + co] = v.y;
            wb[(c4 * 4 + 2) * 68 + co] = v.z;
            wb[(c4 * 4 + 3) * 68 + co] = v.w;
        }
    }
    __syncthreads();

    int tx = tid & 7, ty = tid >> 3;
    int co0 = tx * 8, n0 = ty * 8;
    float* Odst[4] = {O0, O1, O2, O3};

#pragma unroll
    for (int m = 0; m < 4; m++) {
        const float* wb = sW + m * 4352;
        ulonglong2 bi0 = *(const ulonglong2*)&bs[m * 64 + co0];
        ulonglong2 bi1 = *(const ulonglong2*)&bs[m * 64 + co0 + 4];
        ull acc[8][4];
#pragma unroll
        for (int i = 0; i < 8; i++) {
            acc[i][0] = bi0.x; acc[i][1] = bi0.y;
            acc[i][2] = bi1.x; acc[i][3] = bi1.y;
        }
        for (int ci = 0; ci < 64; ci++) {
            ulonglong2 w01 = *(const ulonglong2*)&wb[ci * 68 + co0];
            ulonglong2 w23 = *(const ulonglong2*)&wb[ci * 68 + co0 + 4];
            const float* ap = &sA[n0 * 65 + ci];
#pragma unroll
            for (int i = 0; i < 8; i++) {
                ull a = dup2(ap[i * 65]);
                fma2(acc[i][0], a, w01.x); fma2(acc[i][1], a, w01.y);
                fma2(acc[i][2], a, w23.x); fma2(acc[i][3], a, w23.y);
            }
        }
        float* out = Odst[m];
#pragma unroll
        for (int i = 0; i < 8; i++) {
            size_t node = base + n0 + i;
            float2 p0 = unpack2(acc[i][0]), p1 = unpack2(acc[i][1]);
            float2 p2 = unpack2(acc[i][2]), p3 = unpack2(acc[i][3]);
            *(float4*)(out + node * 64 + co0)     = make_float4(p0.x, p0.y, p1.x, p1.y);
            *(float4*)(out + node * 64 + co0 + 4) = make_float4(p2.x, p2.y, p3.x, p3.y);
        }
    }
}

// ---------------- gcn edge scatter ----------------
__global__ void k_gcn_scatter(const int* __restrict__ ei, const float* __restrict__ ew) {
    int gid = blockIdx.x * blockDim.x + threadIdx.x;  // EE*16
    int e = gid >> 4, qd = gid & 15;
    int r = ei[e], c = ei[EE + e];
    float coeff = g_dinv[r] * g_dinv[c] * ew[2 * e + 1];
    float4 h4 = ((const float4*)g_hw)[(size_t)r * 16 + qd];
    redAdd4(g_acc + (size_t)c * 64 + qd * 4,
            coeff * h4.x, coeff * h4.y, coeff * h4.z, coeff * h4.w);
}

// ---------------- attention alpha + segment max (16 lanes per edge) ----------
__global__ void k_alpha(const int* __restrict__ ei, const float* __restrict__ ew,
                        const float* __restrict__ we) {
    __shared__ float4 wesm4[32];
    int tid = threadIdx.x;
    if (tid < 32) wesm4[tid] = ((const float4*)we)[tid];
    __syncthreads();
    int gid = blockIdx.x * 256 + tid;   // EE*16
    int e = gid >> 4;
    int l = gid & 15;
    int r = ei[e], c = ei[EE + e];
    float2 ewv = ((const float2*)ew)[e];
    float4 q4 = ((const float4*)g_q)[(size_t)c * 16 + l];
    float4 k4 = ((const float4*)g_k)[(size_t)r * 16 + l];
    float4 wa = wesm4[l * 2];
    float4 wb = wesm4[l * 2 + 1];
    float s = q4.x * (k4.x + wa.x * ewv.x + wa.y * ewv.y)
            + q4.y * (k4.y + wa.z * ewv.x + wa.w * ewv.y)
            + q4.z * (k4.z + wb.x * ewv.x + wb.y * ewv.y)
            + q4.w * (k4.w + wb.z * ewv.x + wb.w * ewv.y);
    s += __shfl_xor_sync(0xffffffffu, s, 8);
    s += __shfl_xor_sync(0xffffffffu, s, 4);
    s += __shfl_xor_sync(0xffffffffu, s, 2);
    s += __shfl_xor_sync(0xffffffffu, s, 1);
    if (l == 0) {
        s *= 0.125f;
        g_alpha[e] = s;
        atomicMaxF(&g_amax[c], s);
    }
}

// ---------------- ex + denom ----------------
__global__ void k_denom(const int* __restrict__ ei) {
    int e = blockIdx.x * blockDim.x + threadIdx.x;
    if (e < EE) {
        int c = ei[EE + e];
        float ex = expf(g_alpha[e] - g_amax[c]);
        g_alpha[e] = ex;
        atomicAdd(&g_denom[c], ex);
    }
}

// ---------------- message scatter ----------------
__global__ void k_msg(const int* __restrict__ ei, const float* __restrict__ ew,
                      const float* __restrict__ we) {
    __shared__ float wesm[128];
    int tid = threadIdx.x;
    if (tid < 128) wesm[tid] = we[tid];
    __syncthreads();
    int gid = blockIdx.x * 256 + tid;  // EE*16
    int e = gid >> 4, qd = gid & 15;
    int r = ei[e], c = ei[EE + e];
    float2 ewv = ((const float2*)ew)[e];
    float attn = g_alpha[e] / g_denom[c];
    float4 v4 = ((const float4*)g_v)[(size_t)r * 16 + qd];
    int c0 = qd * 4;
    float m0 = (v4.x + wesm[2 * c0 + 0] * ewv.x + wesm[2 * c0 + 1] * ewv.y) * attn;
    float m1 = (v4.y + wesm[2 * c0 + 2] * ewv.x + wesm[2 * c0 + 3] * ewv.y) * attn;
    float m2 = (v4.z + wesm[2 * c0 + 4] * ewv.x + wesm[2 * c0 + 5] * ewv.y) * attn;
    float m3 = (v4.w + wesm[2 * c0 + 6] * ewv.x + wesm[2 * c0 + 7] * ewv.y) * attn;
    redAdd4(g_acc2 + (size_t)c * 64 + c0, m0, m1, m2, m3);
}

// ---------------- final: bn1(acc2) @ wl.T + bl (warp per node) ---------------
__global__ void k_final(const float* __restrict__ g1, const float* __restrict__ b1,
                        const float* __restrict__ m1, const float* __restrict__ v1,
                        const float* __restrict__ wl, const float* __restrict__ bl,
                        float* __restrict__ out) {
    int t = blockIdx.x * blockDim.x + threadIdx.x;  // NN*32
    int node = t >> 5, lane = t & 31;
    float2 a2 = ((const float2*)g_acc2)[(size_t)node * 32 + lane];
    int c0 = lane * 2;
    float s0 = __ldg(&g1[c0]) * rsqrtf(__ldg(&v1[c0]) + 1e-5f);
    float s1 = __ldg(&g1[c0 + 1]) * rsqrtf(__ldg(&v1[c0 + 1]) + 1e-5f);
    float x0 = (a2.x - __ldg(&m1[c0])) * s0 + __ldg(&b1[c0]);
    float x1 = (a2.y - __ldg(&m1[c0 + 1])) * s1 + __ldg(&b1[c0 + 1]);
    float s = x0 * __ldg(&wl[c0]) + x1 * __ldg(&wl[c0 + 1]);
#pragma unroll
    for (int o = 16; o; o >>= 1) s += __shfl_xor_sync(0xffffffffu, s, o);
    if (lane == 0) out[node] = s + __ldg(&bl[0]);
}

// ---------------- host launcher ----------------
extern "C" void kernel_launch(void* const* d_in, const int* in_sizes, int n_in,
                              void* d_out, int out_size) {
    (void)in_sizes; (void)n_in; (void)out_size;
    const float* x     = (const float*)d_in[0];
    const int*   ei    = (const int*)d_in[1];
    const float* ew    = (const float*)d_in[2];
    const float* cw    = (const float*)d_in[6];
    const float* bn2g  = (const float*)d_in[7];
    const float* bn2b  = (const float*)d_in[8];
    const float* bn2m  = (const float*)d_in[9];
    const float* bn2v  = (const float*)d_in[10];
    const float* gcnw  = (const float*)d_in[11];
    const float* gcnb  = (const float*)d_in[12];
    const float* bn1g  = (const float*)d_in[13];
    const float* bn1b  = (const float*)d_in[14];
    const float* bn1m  = (const float*)d_in[15];
    const float* bn1v  = (const float*)d_in[16];
    const float* wq    = (const float*)d_in[17];
    const float* bq    = (const float*)d_in[18];
    const float* wk    = (const float*)d_in[19];
    const float* bk    = (const float*)d_in[20];
    const float* wv    = (const float*)d_in[21];
    const float* bv    = (const float*)d_in[22];
    const float* we    = (const float*)d_in[23];
    const float* wsk   = (const float*)d_in[24];
    const float* bsk   = (const float*)d_in[25];
    const float* wl    = (const float*)d_in[26];
    const float* bl    = (const float*)d_in[27];

    float *p_h0, *p_q, *p_k, *p_v, *p_acc2;
    cudaGetSymbolAddress((void**)&p_h0,   g_h0);
    cudaGetSymbolAddress((void**)&p_q,    g_q);
    cudaGetSymbolAddress((void**)&p_k,    g_k);
    cudaGetSymbolAddress((void**)&p_v,    g_v);
    cudaGetSymbolAddress((void**)&p_acc2, g_acc2);

    const int gemm1_smem = (256 * 65 + 64 * 68) * 4;
    const int gemm4_smem = (256 * 65 + 4 * 64 * 68 + 256 + 128) * 4;
    cudaFuncSetAttribute(k_gemm1, cudaFuncAttributeMaxDynamicSharedMemorySize, gemm1_smem);
    cudaFuncSetAttribute(k_gemm4, cudaFuncAttributeMaxDynamicSharedMemorySize, gemm4_smem);

    k_init<<<NN / 256, 256>>>();
    k_deg<<<EE / 256, 256>>>(ei, ew);
    k_dinv<<<NN / 256, 256>>>();
    k_wprep<<<72, 256>>>(cw);
    k_conv<<<2048, 256>>>(x, bn2g, bn2b, bn2m, bn2v);
    k_gemm1<<<NN / 256, 256, gemm1_smem>>>(p_h0, gcnw);
    k_gcn_scatter<<<EE * 16 / 256, 256>>>(ei, ew);
    k_gemm4<<<NN / 256, 256, gemm4_smem>>>(gcnb, bn1g, bn1b, bn1m, bn1v,
                                           wq, wk, wv, wsk, bq, bk, bv, bsk,
                                           p_q, p_k, p_v, p_acc2);
    k_alpha<<<EE * 16 / 256, 256>>>(ei, ew, we);
    k_denom<<<EE / 256, 256>>>(ei);
    k_msg<<<EE * 16 / 256, 256>>>(ei, ew, we);
    k_final<<<NN * 32 / 256, 256>>>(bn1g, bn1b, bn1m, bn1v, wl, bl, (float*)d_out);
}

// round 7
// speedup vs baseline: 3.3535x; 1.2037x over previous
#include <cuda_runtime.h>
#include <math.h>

#define NN 131072
#define EE 1048576
#define HH 256
#define WW 256

typedef unsigned long long ull;

// ---------------- scratch (device globals; no allocations) ----------------
__device__ __align__(16) float g_h0[NN * 64];
__device__ __align__(16) float g_hw[NN * 64];
__device__ __align__(16) float g_q[NN * 64];
__device__ __align__(16) float g_k[NN * 64];
__device__ __align__(16) float g_v[NN * 64];
__device__ __align__(16) float g_acc[NN * 64];   // gcn output (pre-bn1)
__device__ __align__(16) float g_acc2[NN * 64];  // skip projection
__device__ __align__(16) float g_deg[NN];
__device__ __align__(16) float g_dinv[NN];
__device__ __align__(16) float g_alpha[EE];      // per-edge alpha, then ex
__device__ __align__(16) float g_wT[9 * 32 * 64];
// CSR (by destination col)
__device__ __align__(16) int    g_cnt[NN];
__device__ __align__(16) int    g_off[NN + 1];
__device__ __align__(16) int    g_cur[NN];
__device__ __align__(16) int    g_bsum[512];
__device__ __align__(16) int    g_bbase[512];
__device__ __align__(16) int    g_src[EE];       // source row per CSR slot
__device__ __align__(16) float2 g_ew2[EE];       // edge_weight pair per CSR slot

__device__ __forceinline__ float eluf(float x) {
    return x > 0.f ? x : 0.1f * expm1f(x);
}
__device__ __forceinline__ void fma2(ull& acc, ull a, ull w) {
    asm("fma.rn.f32x2 %0, %1, %2, %0;" : "+l"(acc) : "l"(a), "l"(w));
}
__device__ __forceinline__ ull dup2(float a) {
    ull r; asm("mov.b64 %0, {%1, %1};" : "=l"(r) : "f"(a)); return r;
}
__device__ __forceinline__ float2 unpack2(ull v) {
    float2 r; asm("mov.b64 {%0, %1}, %2;" : "=f"(r.x), "=f"(r.y) : "l"(v)); return r;
}

// ---------------- init + degree + CSR build ----------------
__global__ void k_init() {
    int i = blockIdx.x * blockDim.x + threadIdx.x;
    if (i < NN) { g_deg[i] = 2.0f; g_cnt[i] = 0; }
}
__global__ void k_deg(const int* __restrict__ ei, const float* __restrict__ ew) {
    int e = blockIdx.x * blockDim.x + threadIdx.x;
    if (e < EE) {
        int c = ei[EE + e];
        atomicAdd(&g_deg[c], ew[2 * e + 1]);
        atomicAdd(&g_cnt[c], 1);
    }
}
__global__ void k_dinv() {
    int i = blockIdx.x * blockDim.x + threadIdx.x;
    if (i < NN) g_dinv[i] = rsqrtf(g_deg[i]);
}
// scan1: 512 blocks x 256; exclusive scan within block, block sums out
__global__ void k_scan1() {
    int b = blockIdx.x, t = threadIdx.x;
    int i = b * 256 + t;
    int v = g_cnt[i];
    int lane = t & 31, wid = t >> 5;
    int x = v;
#pragma unroll
    for (int o = 1; o < 32; o <<= 1) {
        int y = __shfl_up_sync(0xffffffffu, x, o);
        if (lane >= o) x += y;
    }
    __shared__ int wsum[8];
    if (lane == 31) wsum[wid] = x;
    __syncthreads();
    if (t < 8) {
        int w = wsum[t];
#pragma unroll
        for (int o = 1; o < 8; o <<= 1) {
            int y = __shfl_up_sync(0xffu, w, o);
            if (t >= o) w += y;
        }
        wsum[t] = w;
    }
    __syncthreads();
    int base = wid > 0 ? wsum[wid - 1] : 0;
    int incl = base + x;
    g_off[i] = incl - v;
    if (t == 255) g_bsum[b] = incl;
}
// scan2: 1 block x 512 exclusive scan of block sums
__global__ void k_scan2() {
    int t = threadIdx.x;
    int v = g_bsum[t];
    int lane = t & 31, wid = t >> 5;
    int x = v;
#pragma unroll
    for (int o = 1; o < 32; o <<= 1) {
        int y = __shfl_up_sync(0xffffffffu, x, o);
        if (lane >= o) x += y;
    }
    __shared__ int ws[16];
    if (lane == 31) ws[wid] = x;
    __syncthreads();
    if (t < 16) {
        int w = ws[t];
#pragma unroll
        for (int o = 1; o < 16; o <<= 1) {
            int y = __shfl_up_sync(0xffffu, w, o);
            if (t >= o) w += y;
        }
        ws[t] = w;
    }
    __syncthreads();
    int base = wid > 0 ? ws[wid - 1] : 0;
    g_bbase[t] = base + x - v;
}
__global__ void k_scan3() {
    int i = blockIdx.x * 256 + threadIdx.x;
    int v = g_off[i] + g_bbase[i >> 8];
    g_off[i] = v;
    g_cur[i] = v;
    if (i == 0) g_off[NN] = EE;
}
__global__ void k_fill(const int* __restrict__ ei, const float* __restrict__ ew) {
    int e = blockIdx.x * blockDim.x + threadIdx.x;
    if (e < EE) {
        int r = ei[e], c = ei[EE + e];
        int pos = atomicAdd(&g_cur[c], 1);
        g_src[pos] = r;
        g_ew2[pos] = ((const float2*)ew)[e];
    }
}
__global__ void k_wprep(const float* __restrict__ cw) {
    int i = blockIdx.x * blockDim.x + threadIdx.x;
    if (i < 18432) {
        int co = i & 63;
        int ci = (i >> 6) & 31;
        int k  = i >> 11;
        int ky = k / 3, kx = k - ky * 3;
        g_wT[i] = cw[((co * 32 + ci) * 3 + ky) * 3 + kx];
    }
}

// ---------------- conv 3x3 SAME + bn2 + elu (double-buffered weights) --------
__global__ void __launch_bounds__(256)
k_conv(const float* __restrict__ x,
       const float* __restrict__ bg, const float* __restrict__ bb,
       const float* __restrict__ bm, const float* __restrict__ bv) {
    __shared__ __align__(16) float ins[32 * 204];
    __shared__ __align__(16) float wsk[2][2048];

    int tid = threadIdx.x;
    int bid = blockIdx.x;
    int xt = bid & 3;
    int y  = (bid >> 2) & 255;
    int b  = bid >> 10;
    int x0 = xt * 64;

    for (int i = tid; i < 3 * 66 * 32; i += 256) {
        int ci = i & 31;
        int p  = i >> 5;
        int r  = p / 66;
        int px = p - r * 66;
        int yy = y + r - 1;
        int xx = x0 + px - 1;
        float val = 0.f;
        if (yy >= 0 && yy < HH && xx >= 0 && xx < WW)
            val = x[(((size_t)b * HH + yy) * WW + xx) * 32 + ci];
        ins[ci * 204 + r * 68 + px] = val;
    }
    {
        const float4* wsrc = (const float4*)g_wT;
        float4* wdst = (float4*)wsk[0];
#pragma unroll
        for (int i = 0; i < 2; i++) wdst[tid + i * 256] = wsrc[tid + i * 256];
    }
    __syncthreads();

    int tx = tid & 15, ty = tid >> 4;
    int co0 = tx * 4, px0 = ty * 4;

    ull acc[4][2];
#pragma unroll
    for (int i = 0; i < 4; i++) { acc[i][0] = 0ull; acc[i][1] = 0ull; }

#pragma unroll
    for (int k = 0; k < 9; k++) {
        int buf = k & 1;
        int ky = k / 3, kx = k - ky * 3;
        const float* ipk = ins + ky * 68 + px0 + kx;
        const float* wb  = wsk[buf] + co0;
#pragma unroll 4
        for (int ci = 0; ci < 32; ci++) {
            const float* ip = ipk + ci * 204;
            float a0 = ip[0], a1 = ip[1], a2 = ip[2], a3 = ip[3];
            ulonglong2 w = *(const ulonglong2*)(wb + ci * 64);
            ull d0 = dup2(a0), d1 = dup2(a1), d2 = dup2(a2), d3 = dup2(a3);
            fma2(acc[0][0], d0, w.x); fma2(acc[0][1], d0, w.y);
            fma2(acc[1][0], d1, w.x); fma2(acc[1][1], d1, w.y);
            fma2(acc[2][0], d2, w.x); fma2(acc[2][1], d2, w.y);
            fma2(acc[3][0], d3, w.x); fma2(acc[3][1], d3, w.y);
        }
        if (k < 8) {
            const float4* wsrc = (const float4*)(g_wT + (k + 1) * 2048);
            float4* wdst = (float4*)wsk[buf ^ 1];
#pragma unroll
            for (int i = 0; i < 2; i++) wdst[tid + i * 256] = wsrc[tid + i * 256];
        }
        __syncthreads();
    }

    float sc[4], mm[4], bbv[4];
#pragma unroll
    for (int j = 0; j < 4; j++) {
        int c = co0 + j;
        sc[j]  = __ldg(&bg[c]) * rsqrtf(__ldg(&bv[c]) + 1e-5f);
        mm[j]  = __ldg(&bm[c]);
        bbv[j] = __ldg(&bb[c]);
    }
    size_t pixbase = ((size_t)b * HH + y) * WW + x0 + px0;
#pragma unroll
    for (int i = 0; i < 4; i++) {
        float2 p0 = unpack2(acc[i][0]);
        float2 p1 = unpack2(acc[i][1]);
        float r0 = eluf((p0.x - mm[0]) * sc[0] + bbv[0]);
        float r1 = eluf((p0.y - mm[1]) * sc[1] + bbv[1]);
        float r2 = eluf((p1.x - mm[2]) * sc[2] + bbv[2]);
        float r3 = eluf((p1.y - mm[3]) * sc[3] + bbv[3]);
        *(float4*)(g_h0 + (pixbase + i) * 64 + co0) = make_float4(r0, r1, r2, r3);
    }
}

// ---------------- gemm1: hw = h0 @ gcn_w.T -----------------------------------
__global__ void __launch_bounds__(256)
k_gemm1(const float* __restrict__ in, const float* __restrict__ Wm) {
    extern __shared__ float sm[];
    float* sA = sm;               // [256][65]
    float* sW = sm + 256 * 65;    // [64][68]

    int tid = threadIdx.x;
    size_t base = (size_t)blockIdx.x * 256;

    const float4* src = (const float4*)(in + base * 64);
#pragma unroll
    for (int i = 0; i < 16; i++) {
        int idx = tid + i * 256;
        int node = idx >> 4, c4 = idx & 15;
        float4 v = src[idx];
        float* dst = &sA[node * 65 + c4 * 4];
        dst[0] = v.x; dst[1] = v.y; dst[2] = v.z; dst[3] = v.w;
    }
    const float4* w4 = (const float4*)Wm;
#pragma unroll
    for (int i = 0; i < 4; i++) {
        int idx = tid + i * 256;
        int co = idx >> 4, c4 = idx & 15;
        float4 v = w4[idx];
        sW[(c4 * 4 + 0) * 68 + co] = v.x;
        sW[(c4 * 4 + 1) * 68 + co] = v.y;
        sW[(c4 * 4 + 2) * 68 + co] = v.z;
        sW[(c4 * 4 + 3) * 68 + co] = v.w;
    }
    __syncthreads();

    int tx = tid & 7, ty = tid >> 3;
    int co0 = tx * 8, n0 = ty * 8;

    ull acc[8][4];
#pragma unroll
    for (int i = 0; i < 8; i++)
#pragma unroll
        for (int j = 0; j < 4; j++) acc[i][j] = 0ull;

    for (int ci = 0; ci < 64; ci++) {
        ulonglong2 w01 = *(const ulonglong2*)&sW[ci * 68 + co0];
        ulonglong2 w23 = *(const ulonglong2*)&sW[ci * 68 + co0 + 4];
        const float* ap = &sA[n0 * 65 + ci];
#pragma unroll
        for (int i = 0; i < 8; i++) {
            ull a = dup2(ap[i * 65]);
            fma2(acc[i][0], a, w01.x); fma2(acc[i][1], a, w01.y);
            fma2(acc[i][2], a, w23.x); fma2(acc[i][3], a, w23.y);
        }
    }
#pragma unroll
    for (int i = 0; i < 8; i++) {
        size_t node = base + n0 + i;
        float2 p0 = unpack2(acc[i][0]), p1 = unpack2(acc[i][1]);
        float2 p2 = unpack2(acc[i][2]), p3 = unpack2(acc[i][3]);
        *(float4*)(g_hw + node * 64 + co0)     = make_float4(p0.x, p0.y, p1.x, p1.y);
        *(float4*)(g_hw + node * 64 + co0 + 4) = make_float4(p2.x, p2.y, p3.x, p3.y);
    }
}

// ---------------- gcn gather: acc[c] = (2/deg)*hw[c] + sum coeff*hw[r] -------
// 16 lanes per node; 256 thr = 16 nodes/block; grid NN/16
__global__ void __launch_bounds__(256)
k_gcn_gather() {
    int tid = threadIdx.x;
    int l = tid & 15;
    int node = blockIdx.x * 16 + (tid >> 4);
    int beg = g_off[node], end = g_off[node + 1];
    float dinvc = g_dinv[node];
    float s = 2.0f * dinvc * dinvc;
    float4 h4 = ((const float4*)g_hw)[(size_t)node * 16 + l];
    float4 acc = make_float4(s * h4.x, s * h4.y, s * h4.z, s * h4.w);
    for (int p = beg; p < end; p++) {
        int r = g_src[p];
        float ew1 = g_ew2[p].y;
        float coeff = g_dinv[r] * dinvc * ew1;
        float4 v4 = ((const float4*)g_hw)[(size_t)r * 16 + l];
        acc.x += coeff * v4.x; acc.y += coeff * v4.y;
        acc.z += coeff * v4.z; acc.w += coeff * v4.w;
    }
    ((float4*)g_acc)[(size_t)node * 16 + l] = acc;
}

// ---------------- gemm4: q,k,v,skip from elu(bn1(acc+gcn_b)) -----------------
__global__ void __launch_bounds__(256)
k_gemm4(const float* __restrict__ gb,
        const float* __restrict__ g1, const float* __restrict__ b1,
        const float* __restrict__ m1, const float* __restrict__ v1,
        const float* __restrict__ W0, const float* __restrict__ W1,
        const float* __restrict__ W2, const float* __restrict__ W3,
        const float* __restrict__ bb0, const float* __restrict__ bb1,
        const float* __restrict__ bb2, const float* __restrict__ bb3,
        float* __restrict__ O0, float* __restrict__ O1,
        float* __restrict__ O2, float* __restrict__ O3) {
    extern __shared__ float sm[];
    float* sA  = sm;                       // [256][65]
    float* sW  = sm + 16640;               // [4][64][68]
    float* bs  = sm + 16640 + 17408;       // [4][64]
    float* pSc = bs + 256;
    float* pOf = pSc + 64;

    int tid = threadIdx.x;
    size_t base = (size_t)blockIdx.x * 256;

    if (tid < 64) {
        float scv = __ldg(&g1[tid]) * rsqrtf(__ldg(&v1[tid]) + 1e-5f);
        pSc[tid] = scv;
        pOf[tid] = (__ldg(&gb[tid]) - __ldg(&m1[tid])) * scv + __ldg(&b1[tid]);
        bs[tid]       = __ldg(&bb0[tid]);
        bs[64 + tid]  = __ldg(&bb1[tid]);
        bs[128 + tid] = __ldg(&bb2[tid]);
        bs[192 + tid] = __ldg(&bb3[tid]);
    }
    __syncthreads();

    const float4* src = (const float4*)(g_acc + base * 64);
#pragma unroll
    for (int i = 0; i < 16; i++) {
        int idx = tid + i * 256;
        int node = idx >> 4, c4 = idx & 15;
        int c = c4 * 4;
        float4 v = src[idx];
        float* dst = &sA[node * 65 + c];
        dst[0] = eluf(v.x * pSc[c]     + pOf[c]);
        dst[1] = eluf(v.y * pSc[c + 1] + pOf[c + 1]);
        dst[2] = eluf(v.z * pSc[c + 2] + pOf[c + 2]);
        dst[3] = eluf(v.w * pSc[c + 3] + pOf[c + 3]);
    }
    const float* Wsrc[4] = {W0, W1, W2, W3};
#pragma unroll
    for (int m = 0; m < 4; m++) {
        const float4* w4 = (const float4*)Wsrc[m];
#pragma unroll
        for (int i = 0; i < 4; i++) {
            int idx = tid + i * 256;
            int co = idx >> 4, c4 = idx & 15;
            float4 v = w4[idx];
            float* wb = sW + m * 4352;
            wb[(c4 * 4 + 0) * 68 + co] = v.x;
            wb[(c4 * 4 + 1) * 68 + co] = v.y;
            wb[(c4 * 4 + 2) * 68 + co] = v.z;
            wb[(c4 * 4 + 3) * 68 + co] = v.w;
        }
    }
    __syncthreads();

    int tx = tid & 7, ty = tid >> 3;
    int co0 = tx * 8, n0 = ty * 8;
    float* Odst[4] = {O0, O1, O2, O3};

#pragma unroll
    for (int m = 0; m < 4; m++) {
        const float* wb = sW + m * 4352;
        ulonglong2 bi0 = *(const ulonglong2*)&bs[m * 64 + co0];
        ulonglong2 bi1 = *(const ulonglong2*)&bs[m * 64 + co0 + 4];
        ull acc[8][4];
#pragma unroll
        for (int i = 0; i < 8; i++) {
            acc[i][0] = bi0.x; acc[i][1] = bi0.y;
            acc[i][2] = bi1.x; acc[i][3] = bi1.y;
        }
        for (int ci = 0; ci < 64; ci++) {
            ulonglong2 w01 = *(const ulonglong2*)&wb[ci * 68 + co0];
            ulonglong2 w23 = *(const ulonglong2*)&wb[ci * 68 + co0 + 4];
            const float* ap = &sA[n0 * 65 + ci];
#pragma unroll
            for (int i = 0; i < 8; i++) {
                ull a = dup2(ap[i * 65]);
                fma2(acc[i][0], a, w01.x); fma2(acc[i][1], a, w01.y);
                fma2(acc[i][2], a, w23.x); fma2(acc[i][3], a, w23.y);
            }
        }
        float* out = Odst[m];
#pragma unroll
        for (int i = 0; i < 8; i++) {
            size_t node = base + n0 + i;
            float2 p0 = unpack2(acc[i][0]), p1 = unpack2(acc[i][1]);
            float2 p2 = unpack2(acc[i][2]), p3 = unpack2(acc[i][3]);
            *(float4*)(out + node * 64 + co0)     = make_float4(p0.x, p0.y, p1.x, p1.y);
            *(float4*)(out + node * 64 + co0 + 4) = make_float4(p2.x, p2.y, p3.x, p3.y);
        }
    }
}

// ---------------- fused attention: softmax + message + skip + bn1 + wl -------
// 16 lanes per node; grid NN/16; writes final output scalar per node
__global__ void __launch_bounds__(256)
k_attn(const float* __restrict__ we,
       const float* __restrict__ g1, const float* __restrict__ b1,
       const float* __restrict__ m1, const float* __restrict__ v1,
       const float* __restrict__ wl, const float* __restrict__ bl,
       float* __restrict__ out) {
    __shared__ float4 wesm4[32];
    int tid = threadIdx.x;
    if (tid < 32) wesm4[tid] = ((const float4*)we)[tid];
    __syncthreads();

    int l = tid & 15;
    int node = blockIdx.x * 16 + (tid >> 4);
    int beg = g_off[node], end = g_off[node + 1];
    unsigned mask = 0xFFFFu << (tid & 16);

    float4 q4 = ((const float4*)g_q)[(size_t)node * 16 + l];
    float4 wa = wesm4[l * 2];
    float4 wb = wesm4[l * 2 + 1];

    // pass 1: alpha per edge + running max
    float amax = -INFINITY;
    for (int p = beg; p < end; p++) {
        int r = g_src[p];
        float2 ewv = g_ew2[p];
        float4 k4 = ((const float4*)g_k)[(size_t)r * 16 + l];
        float s = q4.x * (k4.x + wa.x * ewv.x + wa.y * ewv.y)
                + q4.y * (k4.y + wa.z * ewv.x + wa.w * ewv.y)
                + q4.z * (k4.z + wb.x * ewv.x + wb.y * ewv.y)
                + q4.w * (k4.w + wb.z * ewv.x + wb.w * ewv.y);
        s += __shfl_xor_sync(mask, s, 8);
        s += __shfl_xor_sync(mask, s, 4);
        s += __shfl_xor_sync(mask, s, 2);
        s += __shfl_xor_sync(mask, s, 1);
        s *= 0.125f;
        if (l == 0) g_alpha[p] = s;
        amax = fmaxf(amax, s);
    }

    // pass 2: ex + denom (lanes strided over edges)
    float dsum = 0.f;
    for (int p = beg + l; p < end; p += 16) {
        float ex = expf(g_alpha[p] - amax);
        g_alpha[p] = ex;
        dsum += ex;
    }
    dsum += __shfl_xor_sync(mask, dsum, 8);
    dsum += __shfl_xor_sync(mask, dsum, 4);
    dsum += __shfl_xor_sync(mask, dsum, 2);
    dsum += __shfl_xor_sync(mask, dsum, 1);
    float inv = 1.0f / dsum;

    // pass 3: weighted message accumulation
    float4 acc = make_float4(0.f, 0.f, 0.f, 0.f);
    for (int p = beg; p < end; p++) {
        int r = g_src[p];
        float2 ewv = g_ew2[p];
        float a = g_alpha[p] * inv;
        float4 v4 = ((const float4*)g_v)[(size_t)r * 16 + l];
        acc.x += (v4.x + wa.x * ewv.x + wa.y * ewv.y) * a;
        acc.y += (v4.y + wa.z * ewv.x + wa.w * ewv.y) * a;
        acc.z += (v4.z + wb.x * ewv.x + wb.y * ewv.y) * a;
        acc.w += (v4.w + wb.z * ewv.x + wb.w * ewv.y) * a;
    }

    // epilogue: + skip, bn1, dot with wl
    float4 skip = ((const float4*)g_acc2)[(size_t)node * 16 + l];
    int c0 = l * 4;
    float part = 0.f;
    float xv[4] = {acc.x + skip.x, acc.y + skip.y, acc.z + skip.z, acc.w + skip.w};
#pragma unroll
    for (int j = 0; j < 4; j++) {
        int c = c0 + j;
        float scv = __ldg(&g1[c]) * rsqrtf(__ldg(&v1[c]) + 1e-5f);
        float bnv = (xv[j] - __ldg(&m1[c])) * scv + __ldg(&b1[c]);
        part += bnv * __ldg(&wl[c]);
    }
    part += __shfl_xor_sync(mask, part, 8);
    part += __shfl_xor_sync(mask, part, 4);
    part += __shfl_xor_sync(mask, part, 2);
    part += __shfl_xor_sync(mask, part, 1);
    if (l == 0) out[node] = part + __ldg(&bl[0]);
}

// ---------------- host launcher ----------------
extern "C" void kernel_launch(void* const* d_in, const int* in_sizes, int n_in,
                              void* d_out, int out_size) {
    (void)in_sizes; (void)n_in; (void)out_size;
    const float* x     = (const float*)d_in[0];
    const int*   ei    = (const int*)d_in[1];
    const float* ew    = (const float*)d_in[2];
    const float* cw    = (const float*)d_in[6];
    const float* bn2g  = (const float*)d_in[7];
    const float* bn2b  = (const float*)d_in[8];
    const float* bn2m  = (const float*)d_in[9];
    const float* bn2v  = (const float*)d_in[10];
    const float* gcnw  = (const float*)d_in[11];
    const float* gcnb  = (const float*)d_in[12];
    const float* bn1g  = (const float*)d_in[13];
    const float* bn1b  = (const float*)d_in[14];
    const float* bn1m  = (const float*)d_in[15];
    const float* bn1v  = (const float*)d_in[16];
    const float* wq    = (const float*)d_in[17];
    const float* bq    = (const float*)d_in[18];
    const float* wk    = (const float*)d_in[19];
    const float* bk    = (const float*)d_in[20];
    const float* wv    = (const float*)d_in[21];
    const float* bv    = (const float*)d_in[22];
    const float* we    = (const float*)d_in[23];
    const float* wsk   = (const float*)d_in[24];
    const float* bsk   = (const float*)d_in[25];
    const float* wl    = (const float*)d_in[26];
    const float* bl    = (const float*)d_in[27];

    float *p_h0, *p_q, *p_k, *p_v, *p_acc2;
    cudaGetSymbolAddress((void**)&p_h0,   g_h0);
    cudaGetSymbolAddress((void**)&p_q,    g_q);
    cudaGetSymbolAddress((void**)&p_k,    g_k);
    cudaGetSymbolAddress((void**)&p_v,    g_v);
    cudaGetSymbolAddress((void**)&p_acc2, g_acc2);

    const int gemm1_smem = (256 * 65 + 64 * 68) * 4;
    const int gemm4_smem = (256 * 65 + 4 * 64 * 68 + 256 + 128) * 4;
    cudaFuncSetAttribute(k_gemm1, cudaFuncAttributeMaxDynamicSharedMemorySize, gemm1_smem);
    cudaFuncSetAttribute(k_gemm4, cudaFuncAttributeMaxDynamicSharedMemorySize, gemm4_smem);

    k_init<<<NN / 256, 256>>>();
    k_deg<<<EE / 256, 256>>>(ei, ew);
    k_scan1<<<512, 256>>>();
    k_scan2<<<1, 512>>>();
    k_scan3<<<512, 256>>>();
    k_fill<<<EE / 256, 256>>>(ei, ew);
    k_dinv<<<NN / 256, 256>>>();
    k_wprep<<<72, 256>>>(cw);
    k_conv<<<2048, 256>>>(x, bn2g, bn2b, bn2m, bn2v);
    k_gemm1<<<NN / 256, 256, gemm1_smem>>>(p_h0, gcnw);
    k_gcn_gather<<<NN / 16, 256>>>();
    k_gemm4<<<NN / 256, 256, gemm4_smem>>>(gcnb, bn1g, bn1b, bn1m, bn1v,
                                           wq, wk, wv, wsk, bq, bk, bv, bsk,
                                           p_q, p_k, p_v, p_acc2);
    k_attn<<<NN / 16, 256>>>(we, bn1g, bn1b, bn1m, bn1v, wl, bl, (float*)d_out);
}